// round 1
// baseline (speedup 1.0000x reference)
#include <cuda_runtime.h>

#define NN 50000
#define NE 1600000
#define IN_F 256
#define OUT_C 128   // H*F
#define NH 4
#define NEG 0.2f

// scratch (allocation-free rule: __device__ globals)
__device__ __align__(16) float g_h[NN * OUT_C];      // projected features  [N,128]
__device__ __align__(16) float g_el[NN * NH];        // left logits  [N,4]
__device__ __align__(16) float g_er[NN * NH];        // right logits [N,4]
__device__ __align__(16) float g_eexp[NE * NH];      // exp(edge score) [E,4]
__device__ __align__(16) float g_denom[NN * NH];     // softmax denominators [N,4]

// ---------------------------------------------------------------------------
// K0: init out = bias (broadcast), denom = 0
// ---------------------------------------------------------------------------
__global__ void init_kernel(const float* __restrict__ bias, float* __restrict__ out) {
    int i = blockIdx.x * blockDim.x + threadIdx.x;
    if (i < NN * OUT_C) out[i] = bias[i & (OUT_C - 1)];
    if (i < NN * NH) g_denom[i] = 0.0f;
}

// ---------------------------------------------------------------------------
// K1: h = feat @ W^T  (tiled fp32), plus el/er per (node, head)
// Tile: 64 nodes x 128 cols, 256 threads, 8x4 per-thread register block.
// ---------------------------------------------------------------------------
#define TN 64
#define KC 32

__global__ __launch_bounds__(256) void proj_kernel(
    const float* __restrict__ feat, const float* __restrict__ W,
    const float* __restrict__ al, const float* __restrict__ ar)
{
    __shared__ float sF[TN][33];     // pitch 33 -> conflict-free scalar access
    __shared__ float sW[KC][132];    // pitch 132 -> 16B-aligned float4 reads

    int t = threadIdx.x;
    int tx = t & 31;         // -> 4 output cols tx*4..tx*4+3
    int ty = t >> 5;         // -> 8 nodes ty*8..ty*8+7
    int node0 = blockIdx.x * TN;

    float acc[8][4];
#pragma unroll
    for (int i = 0; i < 8; i++)
#pragma unroll
        for (int j = 0; j < 4; j++) acc[i][j] = 0.0f;

    for (int k0 = 0; k0 < IN_F; k0 += KC) {
        // feat chunk: 64x32 = 512 float4, 2 per thread (coalesced)
#pragma unroll
        for (int j = 0; j < 2; j++) {
            int f = t + j * 256;             // 0..511
            int r = f >> 3;                  // node row 0..63
            int kq = f & 7;                  // float4 slot 0..7
            int node = node0 + r;
            if (node >= NN) node = NN - 1;   // clamp; stores guarded later
            float4 v = *(const float4*)(feat + (long)node * IN_F + k0 + kq * 4);
            sF[r][kq * 4 + 0] = v.x; sF[r][kq * 4 + 1] = v.y;
            sF[r][kq * 4 + 2] = v.z; sF[r][kq * 4 + 3] = v.w;
        }
        // W chunk transposed to [kk][col]: 128x32 = 1024 float4, 4 per thread
#pragma unroll
        for (int j = 0; j < 4; j++) {
            int g = t + j * 256;             // 0..1023
            int col = g >> 3;                // 0..127
            int kp = g & 7;                  // 0..7
            float4 v = *(const float4*)(W + (long)col * IN_F + k0 + kp * 4);
            sW[kp * 4 + 0][col] = v.x; sW[kp * 4 + 1][col] = v.y;
            sW[kp * 4 + 2][col] = v.z; sW[kp * 4 + 3][col] = v.w;
        }
        __syncthreads();

#pragma unroll
        for (int kk = 0; kk < KC; kk++) {
            float4 b = *(const float4*)(&sW[kk][tx * 4]);   // conflict-free LDS.128
#pragma unroll
            for (int i = 0; i < 8; i++) {
                float a = sF[ty * 8 + i][kk];               // warp-broadcast
                acc[i][0] += a * b.x; acc[i][1] += a * b.y;
                acc[i][2] += a * b.z; acc[i][3] += a * b.w;
            }
        }
        __syncthreads();
    }

    // epilogue: store h, compute el/er via 8-lane shfl reduction per head
    const float4 alv = *(const float4*)(al + tx * 4);
    const float4 arv = *(const float4*)(ar + tx * 4);
    int head = tx >> 3;

#pragma unroll
    for (int i = 0; i < 8; i++) {
        int node = node0 + ty * 8 + i;
        bool ok = node < NN;
        if (ok) {
            float4 v = make_float4(acc[i][0], acc[i][1], acc[i][2], acc[i][3]);
            *(float4*)(g_h + (long)node * OUT_C + tx * 4) = v;
        }
        float pl = acc[i][0] * alv.x + acc[i][1] * alv.y + acc[i][2] * alv.z + acc[i][3] * alv.w;
        float pr = acc[i][0] * arv.x + acc[i][1] * arv.y + acc[i][2] * arv.z + acc[i][3] * arv.w;
        pl += __shfl_down_sync(0xffffffffu, pl, 4);
        pl += __shfl_down_sync(0xffffffffu, pl, 2);
        pl += __shfl_down_sync(0xffffffffu, pl, 1);
        pr += __shfl_down_sync(0xffffffffu, pr, 4);
        pr += __shfl_down_sync(0xffffffffu, pr, 2);
        pr += __shfl_down_sync(0xffffffffu, pr, 1);
        if (ok && (tx & 7) == 0) {
            g_el[node * NH + head] = pl;
            g_er[node * NH + head] = pr;
        }
    }
}

// ---------------------------------------------------------------------------
// K2: per edge: e = leakyrelu(el[src]+er[dst]); eexp = exp(e);
//     denom[dst] += eexp  (vector red). Max-subtraction skipped: |e| <~ 13,
//     exp stays finite and softmax ratios are invariant.
// ---------------------------------------------------------------------------
__global__ void edge_score_kernel(const int* __restrict__ src, const int* __restrict__ dst) {
    int e = blockIdx.x * blockDim.x + threadIdx.x;
    if (e >= NE) return;
    int s = src[e], d = dst[e];
    float4 L = *(const float4*)(g_el + s * NH);
    float4 R = *(const float4*)(g_er + d * NH);
    float4 v;
    v.x = L.x + R.x; v.y = L.y + R.y; v.z = L.z + R.z; v.w = L.w + R.w;
    v.x = v.x >= 0.0f ? v.x : NEG * v.x;
    v.y = v.y >= 0.0f ? v.y : NEG * v.y;
    v.z = v.z >= 0.0f ? v.z : NEG * v.z;
    v.w = v.w >= 0.0f ? v.w : NEG * v.w;
    v.x = __expf(v.x); v.y = __expf(v.y); v.z = __expf(v.z); v.w = __expf(v.w);
    *(float4*)(g_eexp + (long)e * NH) = v;
    asm volatile("red.global.add.v4.f32 [%0], {%1, %2, %3, %4};"
                 :: "l"(g_denom + d * NH), "f"(v.x), "f"(v.y), "f"(v.z), "f"(v.w)
                 : "memory");
}

// ---------------------------------------------------------------------------
// K3: warp per edge: out[dst] += h[src] * (eexp / denom[dst])
// Each lane handles 4 consecutive floats of the 128-wide row; head = lane/8.
// ---------------------------------------------------------------------------
__global__ void aggregate_kernel(const int* __restrict__ src, const int* __restrict__ dst,
                                 float* __restrict__ out)
{
    long gid = (long)blockIdx.x * blockDim.x + threadIdx.x;
    int e = (int)(gid >> 5);
    int lane = (int)(gid & 31);
    if (e >= NE) return;
    int s = src[e], d = dst[e];                              // warp-broadcast loads
    float4 ex4 = *(const float4*)(g_eexp + (long)e * NH);    // broadcast
    float4 dn4 = *(const float4*)(g_denom + d * NH);         // broadcast
    int hd = lane >> 3;
    float ex = (hd == 0) ? ex4.x : (hd == 1) ? ex4.y : (hd == 2) ? ex4.z : ex4.w;
    float dn = (hd == 0) ? dn4.x : (hd == 1) ? dn4.y : (hd == 2) ? dn4.z : dn4.w;
    float a = __fdividef(ex, dn);
    float4 hv = *(const float4*)(g_h + (long)s * OUT_C + lane * 4);  // coalesced 512B/warp
    float4 m = make_float4(hv.x * a, hv.y * a, hv.z * a, hv.w * a);
    asm volatile("red.global.add.v4.f32 [%0], {%1, %2, %3, %4};"
                 :: "l"(out + (long)d * OUT_C + lane * 4), "f"(m.x), "f"(m.y), "f"(m.z), "f"(m.w)
                 : "memory");
}

// ---------------------------------------------------------------------------
extern "C" void kernel_launch(void* const* d_in, const int* in_sizes, int n_in,
                              void* d_out, int out_size) {
    const float* feat = (const float*)d_in[0];
    const float* W    = (const float*)d_in[1];
    const float* al   = (const float*)d_in[2];
    const float* ar   = (const float*)d_in[3];
    const float* bias = (const float*)d_in[4];
    const int*   src  = (const int*)d_in[5];
    const int*   dst  = (const int*)d_in[6];
    float* out = (float*)d_out;

    init_kernel<<<(NN * OUT_C + 255) / 256, 256>>>(bias, out);
    proj_kernel<<<(NN + TN - 1) / TN, 256>>>(feat, W, al, ar);
    edge_score_kernel<<<(NE + 255) / 256, 256>>>(src, dst);
    {
        long total = (long)NE * 32;
        int blocks = (int)((total + 255) / 256);
        aggregate_kernel<<<blocks, 256>>>(src, dst, out);
    }
}

// round 2
// speedup vs baseline: 1.1861x; 1.1861x over previous
#include <cuda_runtime.h>

#define NN 50000
#define NE 1600000
#define IN_F 256
#define OUT_C 128   // H*F
#define NH 4
#define NEG 0.2f

// scratch (allocation-free rule: __device__ globals)
__device__ __align__(16) float g_h[NN * OUT_C];      // projected features  [N,128]
__device__ __align__(16) float g_el[NN * NH];        // left logits  [N,4]
__device__ __align__(16) float g_er[NN * NH];        // right logits [N,4]
__device__ int g_cnt[NN];                            // in-degree histogram
__device__ int g_off[NN + 1];                        // CSR offsets (by dst)
__device__ int g_cur[NN];                            // scatter cursors
__device__ int g_csr_src[NE];                        // src node per CSR slot

// ---------------------------------------------------------------------------
// K0: zero histogram
// ---------------------------------------------------------------------------
__global__ void zero_cnt_kernel() {
    int i = blockIdx.x * blockDim.x + threadIdx.x;
    if (i < NN) g_cnt[i] = 0;
}

// K1: in-degree histogram
__global__ void hist_kernel(const int* __restrict__ dst) {
    int e = blockIdx.x * blockDim.x + threadIdx.x;
    if (e < NE) atomicAdd(&g_cnt[dst[e]], 1);
}

// K2: exclusive scan over 50k counts (single block, 1024 threads)
__global__ __launch_bounds__(1024) void scan_kernel() {
    __shared__ int ssum[1024];
    const int CH = (NN + 1023) / 1024;  // 49
    int t = threadIdx.x;
    int b = t * CH;
    int e = min(b + CH, NN);
    int s = 0;
    for (int i = b; i < e; i++) s += g_cnt[i];
    ssum[t] = s;
    __syncthreads();
    // Hillis-Steele inclusive scan
    for (int off = 1; off < 1024; off <<= 1) {
        int v = (t >= off) ? ssum[t - off] : 0;
        __syncthreads();
        ssum[t] += v;
        __syncthreads();
    }
    int run = ssum[t] - s;  // exclusive prefix for this chunk
    for (int i = b; i < e; i++) {
        int c = g_cnt[i];
        g_off[i] = run;
        g_cur[i] = run;
        run += c;
    }
    if (t == 1023) g_off[NN] = NE;
}

// K3: scatter edges into CSR-by-dst (store src id)
__global__ void scatter_kernel(const int* __restrict__ src, const int* __restrict__ dst) {
    int e = blockIdx.x * blockDim.x + threadIdx.x;
    if (e >= NE) return;
    int d = dst[e];
    int p = atomicAdd(&g_cur[d], 1);
    g_csr_src[p] = src[e];
}

// ---------------------------------------------------------------------------
// K4: h = feat @ W^T  (tiled fp32), plus el/er per (node, head)
// Tile: 64 nodes x 128 cols, 256 threads, 8x4 per-thread register block.
// ---------------------------------------------------------------------------
#define TN 64
#define KC 32

__global__ __launch_bounds__(256) void proj_kernel(
    const float* __restrict__ feat, const float* __restrict__ W,
    const float* __restrict__ al, const float* __restrict__ ar)
{
    __shared__ float sF[TN][33];     // pitch 33 -> conflict-free scalar access
    __shared__ float sW[KC][132];    // pitch 132 -> 16B-aligned float4 reads

    int t = threadIdx.x;
    int tx = t & 31;         // -> 4 output cols tx*4..tx*4+3
    int ty = t >> 5;         // -> 8 nodes ty*8..ty*8+7
    int node0 = blockIdx.x * TN;

    float acc[8][4];
#pragma unroll
    for (int i = 0; i < 8; i++)
#pragma unroll
        for (int j = 0; j < 4; j++) acc[i][j] = 0.0f;

    for (int k0 = 0; k0 < IN_F; k0 += KC) {
#pragma unroll
        for (int j = 0; j < 2; j++) {
            int f = t + j * 256;             // 0..511
            int r = f >> 3;                  // node row 0..63
            int kq = f & 7;                  // float4 slot 0..7
            int node = node0 + r;
            if (node >= NN) node = NN - 1;   // clamp; stores guarded later
            float4 v = *(const float4*)(feat + (long)node * IN_F + k0 + kq * 4);
            sF[r][kq * 4 + 0] = v.x; sF[r][kq * 4 + 1] = v.y;
            sF[r][kq * 4 + 2] = v.z; sF[r][kq * 4 + 3] = v.w;
        }
#pragma unroll
        for (int j = 0; j < 4; j++) {
            int g = t + j * 256;             // 0..1023
            int col = g >> 3;                // 0..127
            int kp = g & 7;                  // 0..7
            float4 v = *(const float4*)(W + (long)col * IN_F + k0 + kp * 4);
            sW[kp * 4 + 0][col] = v.x; sW[kp * 4 + 1][col] = v.y;
            sW[kp * 4 + 2][col] = v.z; sW[kp * 4 + 3][col] = v.w;
        }
        __syncthreads();

#pragma unroll
        for (int kk = 0; kk < KC; kk++) {
            float4 b = *(const float4*)(&sW[kk][tx * 4]);   // conflict-free LDS.128
#pragma unroll
            for (int i = 0; i < 8; i++) {
                float a = sF[ty * 8 + i][kk];               // warp-broadcast
                acc[i][0] += a * b.x; acc[i][1] += a * b.y;
                acc[i][2] += a * b.z; acc[i][3] += a * b.w;
            }
        }
        __syncthreads();
    }

    const float4 alv = *(const float4*)(al + tx * 4);
    const float4 arv = *(const float4*)(ar + tx * 4);
    int head = tx >> 3;

#pragma unroll
    for (int i = 0; i < 8; i++) {
        int node = node0 + ty * 8 + i;
        bool ok = node < NN;
        if (ok) {
            float4 v = make_float4(acc[i][0], acc[i][1], acc[i][2], acc[i][3]);
            *(float4*)(g_h + (long)node * OUT_C + tx * 4) = v;
        }
        float pl = acc[i][0] * alv.x + acc[i][1] * alv.y + acc[i][2] * alv.z + acc[i][3] * alv.w;
        float pr = acc[i][0] * arv.x + acc[i][1] * arv.y + acc[i][2] * arv.z + acc[i][3] * arv.w;
        pl += __shfl_down_sync(0xffffffffu, pl, 4);
        pl += __shfl_down_sync(0xffffffffu, pl, 2);
        pl += __shfl_down_sync(0xffffffffu, pl, 1);
        pr += __shfl_down_sync(0xffffffffu, pr, 4);
        pr += __shfl_down_sync(0xffffffffu, pr, 2);
        pr += __shfl_down_sync(0xffffffffu, pr, 1);
        if (ok && (tx & 7) == 0) {
            g_el[node * NH + head] = pl;
            g_er[node * NH + head] = pr;
        }
    }
}

// ---------------------------------------------------------------------------
// K5: fused softmax + aggregation, warp per destination node, NO atomics.
// Softmax max-subtraction skipped (|e| <~ 13, exp finite, ratios invariant);
// normalization deferred: out = (sum_e exp(e)*h[src]) / (sum_e exp(e)).
// ---------------------------------------------------------------------------
__global__ __launch_bounds__(256) void agg_kernel(const float* __restrict__ bias,
                                                  float* __restrict__ out)
{
    __shared__ float4 s_ex[8][32];
    __shared__ int    s_src[8][32];

    int wib  = threadIdx.x >> 5;
    int lane = threadIdx.x & 31;
    int node = blockIdx.x * 8 + wib;
    if (node >= NN) return;

    int beg = g_off[node];
    int end = g_off[node + 1];
    const float4 er4 = *(const float4*)(g_er + node * NH);

    float4 dsum = make_float4(0.f, 0.f, 0.f, 0.f);
    float4 acc  = make_float4(0.f, 0.f, 0.f, 0.f);
    int hd = lane >> 3;

    for (int c = beg; c < end; c += 32) {
        int n = end - c;
        if (n > 32) n = 32;

        // chunk phase: lane-parallel edge scores
        float4 v = make_float4(0.f, 0.f, 0.f, 0.f);
        int s = 0;
        if (lane < n) {
            s = g_csr_src[c + lane];
            float4 L = *(const float4*)(g_el + s * NH);
            v.x = L.x + er4.x; v.y = L.y + er4.y;
            v.z = L.z + er4.z; v.w = L.w + er4.w;
            v.x = v.x >= 0.f ? v.x : NEG * v.x;
            v.y = v.y >= 0.f ? v.y : NEG * v.y;
            v.z = v.z >= 0.f ? v.z : NEG * v.z;
            v.w = v.w >= 0.f ? v.w : NEG * v.w;
            v.x = __expf(v.x); v.y = __expf(v.y);
            v.z = __expf(v.z); v.w = __expf(v.w);
            dsum.x += v.x; dsum.y += v.y; dsum.z += v.z; dsum.w += v.w;
        }
        s_ex[wib][lane] = v;
        s_src[wib][lane] = s;
        __syncwarp();

        // gather phase: warp cooperates on each edge's 512B h row
        if (n == 32) {
#pragma unroll 8
            for (int j = 0; j < 32; j++) {
                int sj = s_src[wib][j];
                float4 ex = s_ex[wib][j];
                float a = (hd == 0) ? ex.x : (hd == 1) ? ex.y : (hd == 2) ? ex.z : ex.w;
                float4 hv = *(const float4*)(g_h + (long)sj * OUT_C + lane * 4);
                acc.x += hv.x * a; acc.y += hv.y * a;
                acc.z += hv.z * a; acc.w += hv.w * a;
            }
        } else {
            for (int j = 0; j < n; j++) {
                int sj = s_src[wib][j];
                float4 ex = s_ex[wib][j];
                float a = (hd == 0) ? ex.x : (hd == 1) ? ex.y : (hd == 2) ? ex.z : ex.w;
                float4 hv = *(const float4*)(g_h + (long)sj * OUT_C + lane * 4);
                acc.x += hv.x * a; acc.y += hv.y * a;
                acc.z += hv.z * a; acc.w += hv.w * a;
            }
        }
        __syncwarp();
    }

    // warp-reduce denominators (all lanes end with the totals)
#pragma unroll
    for (int o = 16; o; o >>= 1) {
        dsum.x += __shfl_xor_sync(0xffffffffu, dsum.x, o);
        dsum.y += __shfl_xor_sync(0xffffffffu, dsum.y, o);
        dsum.z += __shfl_xor_sync(0xffffffffu, dsum.z, o);
        dsum.w += __shfl_xor_sync(0xffffffffu, dsum.w, o);
    }
    float dn = (hd == 0) ? dsum.x : (hd == 1) ? dsum.y : (hd == 2) ? dsum.z : dsum.w;
    float rdn = (dn > 0.f) ? (1.0f / dn) : 1.0f;

    const float4 b4 = *(const float4*)(bias + lane * 4);
    float4 o4;
    o4.x = acc.x * rdn + b4.x;
    o4.y = acc.y * rdn + b4.y;
    o4.z = acc.z * rdn + b4.z;
    o4.w = acc.w * rdn + b4.w;
    *(float4*)(out + (long)node * OUT_C + lane * 4) = o4;
}

// ---------------------------------------------------------------------------
extern "C" void kernel_launch(void* const* d_in, const int* in_sizes, int n_in,
                              void* d_out, int out_size) {
    const float* feat = (const float*)d_in[0];
    const float* W    = (const float*)d_in[1];
    const float* al   = (const float*)d_in[2];
    const float* ar   = (const float*)d_in[3];
    const float* bias = (const float*)d_in[4];
    const int*   src  = (const int*)d_in[5];
    const int*   dst  = (const int*)d_in[6];
    float* out = (float*)d_out;

    zero_cnt_kernel<<<(NN + 255) / 256, 256>>>();
    hist_kernel<<<(NE + 255) / 256, 256>>>(dst);
    scan_kernel<<<1, 1024>>>();
    scatter_kernel<<<(NE + 255) / 256, 256>>>(src, dst);
    proj_kernel<<<(NN + TN - 1) / TN, 256>>>(feat, W, al, ar);
    agg_kernel<<<(NN + 7) / 8, 256>>>(bias, out);
}

// round 4
// speedup vs baseline: 1.3064x; 1.1014x over previous
#include <cuda_runtime.h>
#include <cuda_bf16.h>
#include <cstdint>

#define NN 50000
#define NE 1600000
#define IN_F 256
#define OUT_C 128   // H*F
#define NH 4
#define NEG 0.2f

// scratch (allocation-free rule: __device__ globals)
__device__ __align__(16) float g_h[NN * OUT_C];      // projected features  [N,128]
__device__ __align__(16) float g_el[NN * NH];        // left logits  [N,4]
__device__ __align__(16) float g_er[NN * NH];        // right logits [N,4]
__device__ int g_cnt[NN];                            // in-degree histogram
__device__ int g_off[NN + 1];                        // CSR offsets (by dst)
__device__ int g_cur[NN];                            // scatter cursors
__device__ int g_csr_src[NE];                        // src node per CSR slot

// ---------------------------------------------------------------------------
// CSR build: zero -> hist -> scan -> scatter (hist/scatter 4-way ILP on atomics)
// ---------------------------------------------------------------------------
__global__ void zero_cnt_kernel() {
    int i = blockIdx.x * blockDim.x + threadIdx.x;
    if (i < NN) g_cnt[i] = 0;
}

__global__ void hist_kernel(const int* __restrict__ dst) {
    int base = (blockIdx.x * blockDim.x + threadIdx.x) * 4;
#pragma unroll
    for (int j = 0; j < 4; j++) {
        int e = base + j;
        if (e < NE) atomicAdd(&g_cnt[dst[e]], 1);
    }
}

__global__ __launch_bounds__(1024) void scan_kernel() {
    __shared__ int ssum[1024];
    const int CH = (NN + 1023) / 1024;  // 49
    int t = threadIdx.x;
    int b = t * CH;
    int e = min(b + CH, NN);
    int s = 0;
    for (int i = b; i < e; i++) s += g_cnt[i];
    ssum[t] = s;
    __syncthreads();
    for (int off = 1; off < 1024; off <<= 1) {
        int v = (t >= off) ? ssum[t - off] : 0;
        __syncthreads();
        ssum[t] += v;
        __syncthreads();
    }
    int run = ssum[t] - s;
    for (int i = b; i < e; i++) {
        int c = g_cnt[i];
        g_off[i] = run;
        g_cur[i] = run;
        run += c;
    }
    if (t == 1023) g_off[NN] = NE;
}

__global__ void scatter_kernel(const int* __restrict__ src, const int* __restrict__ dst) {
    int base = (blockIdx.x * blockDim.x + threadIdx.x) * 4;
    int d[4], s[4], p[4];
#pragma unroll
    for (int j = 0; j < 4; j++) {
        int e = base + j;
        if (e < NE) { d[j] = dst[e]; s[j] = src[e]; }
    }
#pragma unroll
    for (int j = 0; j < 4; j++)
        if (base + j < NE) p[j] = atomicAdd(&g_cur[d[j]], 1);
#pragma unroll
    for (int j = 0; j < 4; j++)
        if (base + j < NE) g_csr_src[p[j]] = s[j];
}

// ---------------------------------------------------------------------------
// Projection: h = feat @ W^T via bf16-split tensor-core GEMM.
// A = Ahi+Alo, B = Bhi+Blo (bf16);  C ~= Ahi*Bhi + Ahi*Blo + Alo*Bhi  (err ~2^-18)
// Block tile 128x128, K-step 32, 8 warps (4m x 2n), warp tile 32x64.
// smem pitch 40 bf16 (80 B) -> conflict-free ldmatrix.
// ---------------------------------------------------------------------------
#define SPIT 40

__device__ __forceinline__ void bsplit(float x, __nv_bfloat16& hi, __nv_bfloat16& lo) {
    hi = __float2bfloat16_rn(x);
    lo = __float2bfloat16_rn(x - __bfloat162float(hi));
}

__device__ __forceinline__ void ldm_x4(unsigned* r, const __nv_bfloat16* p) {
    unsigned a = (unsigned)__cvta_generic_to_shared(p);
    asm volatile("ldmatrix.sync.aligned.m8n8.x4.shared.b16 {%0,%1,%2,%3}, [%4];"
                 : "=r"(r[0]), "=r"(r[1]), "=r"(r[2]), "=r"(r[3]) : "r"(a));
}

__device__ __forceinline__ void mma16816(float* c, const unsigned* a,
                                         unsigned b0, unsigned b1) {
    asm volatile("mma.sync.aligned.m16n8k16.row.col.f32.bf16.bf16.f32 "
                 "{%0,%1,%2,%3},{%4,%5,%6,%7},{%8,%9},{%0,%1,%2,%3};"
                 : "+f"(c[0]), "+f"(c[1]), "+f"(c[2]), "+f"(c[3])
                 : "r"(a[0]), "r"(a[1]), "r"(a[2]), "r"(a[3]), "r"(b0), "r"(b1));
}

__global__ __launch_bounds__(256) void proj_mma_kernel(
    const float* __restrict__ feat, const float* __restrict__ W)
{
    __shared__ __nv_bfloat16 sAhi[128][SPIT];
    __shared__ __nv_bfloat16 sAlo[128][SPIT];
    __shared__ __nv_bfloat16 sBhi[128][SPIT];
    __shared__ __nv_bfloat16 sBlo[128][SPIT];

    int t = threadIdx.x;
    int lane = t & 31;
    int wid = t >> 5;
    int wm = wid & 3;
    int wn = wid >> 2;
    int node0 = blockIdx.x * 128;

    float acc[2][8][4];
#pragma unroll
    for (int i = 0; i < 2; i++)
#pragma unroll
        for (int j = 0; j < 8; j++)
#pragma unroll
            for (int q = 0; q < 4; q++) acc[i][j][q] = 0.0f;

    for (int k0 = 0; k0 < IN_F; k0 += 32) {
        // A tile: 128 rows x 32 cols fp32 -> split bf16
#pragma unroll
        for (int j = 0; j < 4; j++) {
            int id = t + j * 256;            // 0..1023
            int row = id >> 3;
            int c4 = (id & 7) * 4;
            int node = node0 + row;
            if (node >= NN) node = NN - 1;
            float4 v = *(const float4*)(feat + (long)node * IN_F + k0 + c4);
            bsplit(v.x, sAhi[row][c4 + 0], sAlo[row][c4 + 0]);
            bsplit(v.y, sAhi[row][c4 + 1], sAlo[row][c4 + 1]);
            bsplit(v.z, sAhi[row][c4 + 2], sAlo[row][c4 + 2]);
            bsplit(v.w, sAhi[row][c4 + 3], sAlo[row][c4 + 3]);
        }
        // B tile: W rows are output cols, exactly 128
#pragma unroll
        for (int j = 0; j < 4; j++) {
            int id = t + j * 256;
            int row = id >> 3;
            int c4 = (id & 7) * 4;
            float4 v = *(const float4*)(W + (long)row * IN_F + k0 + c4);
            bsplit(v.x, sBhi[row][c4 + 0], sBlo[row][c4 + 0]);
            bsplit(v.y, sBhi[row][c4 + 1], sBlo[row][c4 + 1]);
            bsplit(v.z, sBhi[row][c4 + 2], sBlo[row][c4 + 2]);
            bsplit(v.w, sBhi[row][c4 + 3], sBlo[row][c4 + 3]);
        }
        __syncthreads();

#pragma unroll
        for (int ks = 0; ks < 2; ks++) {
            int koff = ks * 16;
            unsigned ahi[2][4], alo[2][4];
#pragma unroll
            for (int mt = 0; mt < 2; mt++) {
                int row = wm * 32 + mt * 16 + (lane & 15);
                int col = koff + (lane >> 4) * 8;
                ldm_x4(ahi[mt], &sAhi[row][col]);
                ldm_x4(alo[mt], &sAlo[row][col]);
            }
            unsigned bhi[4][4], blo[4][4];
#pragma unroll
            for (int ng = 0; ng < 4; ng++) {
                int row = wn * 64 + ng * 16 + (lane & 7) + ((lane >> 4) << 3);
                int col = koff + ((lane >> 3) & 1) * 8;
                ldm_x4(bhi[ng], &sBhi[row][col]);
                ldm_x4(blo[ng], &sBlo[row][col]);
            }
#pragma unroll
            for (int mt = 0; mt < 2; mt++)
#pragma unroll
                for (int ng = 0; ng < 4; ng++)
#pragma unroll
                    for (int hf = 0; hf < 2; hf++) {
                        float* c = acc[mt][ng * 2 + hf];
                        mma16816(c, ahi[mt], bhi[ng][hf * 2], bhi[ng][hf * 2 + 1]);
                        mma16816(c, ahi[mt], blo[ng][hf * 2], blo[ng][hf * 2 + 1]);
                        mma16816(c, alo[mt], bhi[ng][hf * 2], bhi[ng][hf * 2 + 1]);
                    }
        }
        __syncthreads();
    }

    // epilogue: C fragment -> g_h (fp32)
    int grp = lane >> 2;
    int tg = lane & 3;
#pragma unroll
    for (int mt = 0; mt < 2; mt++) {
#pragma unroll
        for (int nt = 0; nt < 8; nt++) {
            int row = node0 + wm * 32 + mt * 16 + grp;
            int col = wn * 64 + nt * 8 + tg * 2;
            float* c = acc[mt][nt];
            if (row < NN) {
                *(float2*)(g_h + (long)row * OUT_C + col) = make_float2(c[0], c[1]);
            }
            if (row + 8 < NN) {
                *(float2*)(g_h + (long)(row + 8) * OUT_C + col) = make_float2(c[2], c[3]);
            }
        }
    }
}

// ---------------------------------------------------------------------------
// el/er: per (node, head) dot of h row-chunk with attn vectors (L2-resident)
// ---------------------------------------------------------------------------
__global__ void elr_kernel(const float* __restrict__ al, const float* __restrict__ ar) {
    int i = blockIdx.x * blockDim.x + threadIdx.x;   // node*NH + head
    if (i >= NN * NH) return;
    int node = i >> 2;
    int head = i & 3;
    const float* hp = g_h + (long)node * OUT_C + head * 32;
    float sl = 0.f, sr = 0.f;
#pragma unroll
    for (int j = 0; j < 8; j++) {
        float4 v = *(const float4*)(hp + j * 4);
        float4 a = *(const float4*)(al + head * 32 + j * 4);
        float4 b = *(const float4*)(ar + head * 32 + j * 4);
        sl += v.x * a.x + v.y * a.y + v.z * a.z + v.w * a.w;
        sr += v.x * b.x + v.y * b.y + v.z * b.z + v.w * b.w;
    }
    g_el[i] = sl;
    g_er[i] = sr;
}

// ---------------------------------------------------------------------------
// Fused softmax + aggregation, warp per destination node, NO atomics.
// Max-subtraction skipped (|e| <~ 13, exp finite, ratios invariant);
// normalization deferred: out = (sum_e exp(e)*h[src]) / (sum_e exp(e)).
// ---------------------------------------------------------------------------
__global__ __launch_bounds__(256) void agg_kernel(const float* __restrict__ bias,
                                                  float* __restrict__ out)
{
    __shared__ float4 s_ex[8][32];
    __shared__ int    s_src[8][32];

    int wib  = threadIdx.x >> 5;
    int lane = threadIdx.x & 31;
    int node = blockIdx.x * 8 + wib;
    if (node >= NN) return;

    int beg = g_off[node];
    int end = g_off[node + 1];
    const float4 er4 = *(const float4*)(g_er + node * NH);

    float4 dsum = make_float4(0.f, 0.f, 0.f, 0.f);
    float4 acc  = make_float4(0.f, 0.f, 0.f, 0.f);
    int hd = lane >> 3;

    for (int c = beg; c < end; c += 32) {
        int n = end - c;
        if (n > 32) n = 32;

        float4 v = make_float4(0.f, 0.f, 0.f, 0.f);
        int s = 0;
        if (lane < n) {
            s = g_csr_src[c + lane];
            float4 L = *(const float4*)(g_el + s * NH);
            v.x = L.x + er4.x; v.y = L.y + er4.y;
            v.z = L.z + er4.z; v.w = L.w + er4.w;
            v.x = v.x >= 0.f ? v.x : NEG * v.x;
            v.y = v.y >= 0.f ? v.y : NEG * v.y;
            v.z = v.z >= 0.f ? v.z : NEG * v.z;
            v.w = v.w >= 0.f ? v.w : NEG * v.w;
            v.x = __expf(v.x); v.y = __expf(v.y);
            v.z = __expf(v.z); v.w = __expf(v.w);
            dsum.x += v.x; dsum.y += v.y; dsum.z += v.z; dsum.w += v.w;
        }
        s_ex[wib][lane] = v;
        s_src[wib][lane] = s;
        __syncwarp();

        if (n == 32) {
#pragma unroll 8
            for (int j = 0; j < 32; j++) {
                int sj = s_src[wib][j];
                float4 ex = s_ex[wib][j];
                float a = (hd == 0) ? ex.x : (hd == 1) ? ex.y : (hd == 2) ? ex.z : ex.w;
                float4 hv = *(const float4*)(g_h + (long)sj * OUT_C + lane * 4);
                acc.x += hv.x * a; acc.y += hv.y * a;
                acc.z += hv.z * a; acc.w += hv.w * a;
            }
        } else {
            for (int j = 0; j < n; j++) {
                int sj = s_src[wib][j];
                float4 ex = s_ex[wib][j];
                float a = (hd == 0) ? ex.x : (hd == 1) ? ex.y : (hd == 2) ? ex.z : ex.w;
                float4 hv = *(const float4*)(g_h + (long)sj * OUT_C + lane * 4);
                acc.x += hv.x * a; acc.y += hv.y * a;
                acc.z += hv.z * a; acc.w += hv.w * a;
            }
        }
        __syncwarp();
    }

#pragma unroll
    for (int o = 16; o; o >>= 1) {
        dsum.x += __shfl_xor_sync(0xffffffffu, dsum.x, o);
        dsum.y += __shfl_xor_sync(0xffffffffu, dsum.y, o);
        dsum.z += __shfl_xor_sync(0xffffffffu, dsum.z, o);
        dsum.w += __shfl_xor_sync(0xffffffffu, dsum.w, o);
    }
    float dn = (hd == 0) ? dsum.x : (hd == 1) ? dsum.y : (hd == 2) ? dsum.z : dsum.w;
    float rdn = (dn > 0.f) ? (1.0f / dn) : 1.0f;

    const float4 b4 = *(const float4*)(bias + lane * 4);
    float4 o4;
    o4.x = acc.x * rdn + b4.x;
    o4.y = acc.y * rdn + b4.y;
    o4.z = acc.z * rdn + b4.z;
    o4.w = acc.w * rdn + b4.w;
    *(float4*)(out + (long)node * OUT_C + lane * 4) = o4;
}

// ---------------------------------------------------------------------------
extern "C" void kernel_launch(void* const* d_in, const int* in_sizes, int n_in,
                              void* d_out, int out_size) {
    const float* feat = (const float*)d_in[0];
    const float* W    = (const float*)d_in[1];
    const float* al   = (const float*)d_in[2];
    const float* ar   = (const float*)d_in[3];
    const float* bias = (const float*)d_in[4];
    const int*   src  = (const int*)d_in[5];
    const int*   dst  = (const int*)d_in[6];
    float* out = (float*)d_out;

    zero_cnt_kernel<<<(NN + 255) / 256, 256>>>();
    hist_kernel<<<(NE / 4 + 255) / 256, 256>>>(dst);
    scan_kernel<<<1, 1024>>>();
    scatter_kernel<<<(NE / 4 + 255) / 256, 256>>>(src, dst);
    proj_mma_kernel<<<(NN + 127) / 128, 256>>>(feat, W);
    elr_kernel<<<(NN * NH + 255) / 256, 256>>>(al, ar);
    agg_kernel<<<(NN + 7) / 8, 256>>>(bias, out);
}

// round 6
// speedup vs baseline: 1.4506x; 1.1104x over previous
#include <cuda_runtime.h>
#include <cuda_bf16.h>
#include <cuda_fp16.h>
#include <cstdint>

#define NN 50000
#define NE 1600000
#define IN_F 256
#define OUT_C 128   // H*F
#define NH 4
#define NEG 0.2f

// scratch (allocation-free rule: __device__ globals)
__device__ __align__(16) float  g_h[NN * OUT_C];     // projected features fp32 [N,128]
__device__ __align__(16) __half g_hh[NN * OUT_C];    // fp16 copy for gather   [N,128]
__device__ __align__(16) float  g_el[NN * NH];       // left logits  [N,4]
__device__ __align__(16) float  g_er[NN * NH];       // right logits [N,4]
__device__ int g_cnt[NN];                            // in-degree histogram
__device__ int g_off[NN + 1];                        // CSR offsets (by dst)
__device__ int g_rank[NE];                           // edge rank within its dst
__device__ int g_csr_src[NE];                        // src node per CSR slot

// ---------------------------------------------------------------------------
// CSR build: zero -> hist(+rank) -> scan -> scatter (atomic-free scatter)
// ---------------------------------------------------------------------------
__global__ void zero_cnt_kernel() {
    int i = blockIdx.x * blockDim.x + threadIdx.x;
    if (i < NN) g_cnt[i] = 0;
}

__global__ void hist_kernel(const int* __restrict__ dst) {
    int base = (blockIdx.x * blockDim.x + threadIdx.x) * 4;
    int d[4], r[4];
#pragma unroll
    for (int j = 0; j < 4; j++) {
        int e = base + j;
        if (e < NE) d[j] = dst[e];
    }
#pragma unroll
    for (int j = 0; j < 4; j++)
        if (base + j < NE) r[j] = atomicAdd(&g_cnt[d[j]], 1);
#pragma unroll
    for (int j = 0; j < 4; j++)
        if (base + j < NE) g_rank[base + j] = r[j];
}

__global__ __launch_bounds__(1024) void scan_kernel() {
    __shared__ int ssum[1024];
    const int CH = (NN + 1023) / 1024;  // 49
    int t = threadIdx.x;
    int b = t * CH;
    int e = min(b + CH, NN);
    int s = 0;
    for (int i = b; i < e; i++) s += g_cnt[i];
    ssum[t] = s;
    __syncthreads();
    for (int off = 1; off < 1024; off <<= 1) {
        int v = (t >= off) ? ssum[t - off] : 0;
        __syncthreads();
        ssum[t] += v;
        __syncthreads();
    }
    int run = ssum[t] - s;
    for (int i = b; i < e; i++) {
        int c = g_cnt[i];
        g_off[i] = run;
        run += c;
    }
    if (t == 1023) g_off[NN] = NE;
}

__global__ void scatter_kernel(const int* __restrict__ src, const int* __restrict__ dst) {
    int base = (blockIdx.x * blockDim.x + threadIdx.x) * 4;
#pragma unroll
    for (int j = 0; j < 4; j++) {
        int e = base + j;
        if (e < NE) {
            int p = g_off[dst[e]] + g_rank[e];
            g_csr_src[p] = src[e];
        }
    }
}

// ---------------------------------------------------------------------------
// Projection: h = feat @ W^T via bf16-split tensor-core GEMM.
// A = Ahi+Alo, B = Bhi+Blo (bf16);  C ~= Ahi*Bhi + Ahi*Blo + Alo*Bhi  (err ~2^-18)
// Block tile 128x128, K-step 32, 8 warps (4m x 2n), warp tile 32x64.
// smem pitch 40 bf16 (80 B) -> conflict-free ldmatrix.
// ---------------------------------------------------------------------------
#define SPIT 40

__device__ __forceinline__ void bsplit(float x, __nv_bfloat16& hi, __nv_bfloat16& lo) {
    hi = __float2bfloat16_rn(x);
    lo = __float2bfloat16_rn(x - __bfloat162float(hi));
}

__device__ __forceinline__ void ldm_x4(unsigned* r, const __nv_bfloat16* p) {
    unsigned a = (unsigned)__cvta_generic_to_shared(p);
    asm volatile("ldmatrix.sync.aligned.m8n8.x4.shared.b16 {%0,%1,%2,%3}, [%4];"
                 : "=r"(r[0]), "=r"(r[1]), "=r"(r[2]), "=r"(r[3]) : "r"(a));
}

__device__ __forceinline__ void mma16816(float* c, const unsigned* a,
                                         unsigned b0, unsigned b1) {
    asm volatile("mma.sync.aligned.m16n8k16.row.col.f32.bf16.bf16.f32 "
                 "{%0,%1,%2,%3},{%4,%5,%6,%7},{%8,%9},{%0,%1,%2,%3};"
                 : "+f"(c[0]), "+f"(c[1]), "+f"(c[2]), "+f"(c[3])
                 : "r"(a[0]), "r"(a[1]), "r"(a[2]), "r"(a[3]), "r"(b0), "r"(b1));
}

__global__ __launch_bounds__(256) void proj_mma_kernel(
    const float* __restrict__ feat, const float* __restrict__ W)
{
    __shared__ __nv_bfloat16 sAhi[128][SPIT];
    __shared__ __nv_bfloat16 sAlo[128][SPIT];
    __shared__ __nv_bfloat16 sBhi[128][SPIT];
    __shared__ __nv_bfloat16 sBlo[128][SPIT];

    int t = threadIdx.x;
    int lane = t & 31;
    int wid = t >> 5;
    int wm = wid & 3;
    int wn = wid >> 2;
    int node0 = blockIdx.x * 128;

    float acc[2][8][4];
#pragma unroll
    for (int i = 0; i < 2; i++)
#pragma unroll
        for (int j = 0; j < 8; j++)
#pragma unroll
            for (int q = 0; q < 4; q++) acc[i][j][q] = 0.0f;

    for (int k0 = 0; k0 < IN_F; k0 += 32) {
        // A tile: 128 rows x 32 cols fp32 -> split bf16
#pragma unroll
        for (int j = 0; j < 4; j++) {
            int id = t + j * 256;            // 0..1023
            int row = id >> 3;
            int c4 = (id & 7) * 4;
            int node = node0 + row;
            if (node >= NN) node = NN - 1;
            float4 v = *(const float4*)(feat + (long)node * IN_F + k0 + c4);
            bsplit(v.x, sAhi[row][c4 + 0], sAlo[row][c4 + 0]);
            bsplit(v.y, sAhi[row][c4 + 1], sAlo[row][c4 + 1]);
            bsplit(v.z, sAhi[row][c4 + 2], sAlo[row][c4 + 2]);
            bsplit(v.w, sAhi[row][c4 + 3], sAlo[row][c4 + 3]);
        }
        // B tile: W rows are output cols, exactly 128
#pragma unroll
        for (int j = 0; j < 4; j++) {
            int id = t + j * 256;
            int row = id >> 3;
            int c4 = (id & 7) * 4;
            float4 v = *(const float4*)(W + (long)row * IN_F + k0 + c4);
            bsplit(v.x, sBhi[row][c4 + 0], sBlo[row][c4 + 0]);
            bsplit(v.y, sBhi[row][c4 + 1], sBlo[row][c4 + 1]);
            bsplit(v.z, sBhi[row][c4 + 2], sBlo[row][c4 + 2]);
            bsplit(v.w, sBhi[row][c4 + 3], sBlo[row][c4 + 3]);
        }
        __syncthreads();

#pragma unroll
        for (int ks = 0; ks < 2; ks++) {
            int koff = ks * 16;
            unsigned ahi[2][4], alo[2][4];
#pragma unroll
            for (int mt = 0; mt < 2; mt++) {
                int row = wm * 32 + mt * 16 + (lane & 15);
                int col = koff + (lane >> 4) * 8;
                ldm_x4(ahi[mt], &sAhi[row][col]);
                ldm_x4(alo[mt], &sAlo[row][col]);
            }
            unsigned bhi[4][4], blo[4][4];
#pragma unroll
            for (int ng = 0; ng < 4; ng++) {
                int row = wn * 64 + ng * 16 + (lane & 7) + ((lane >> 4) << 3);
                int col = koff + ((lane >> 3) & 1) * 8;
                ldm_x4(bhi[ng], &sBhi[row][col]);
                ldm_x4(blo[ng], &sBlo[row][col]);
            }
#pragma unroll
            for (int mt = 0; mt < 2; mt++)
#pragma unroll
                for (int ng = 0; ng < 4; ng++)
#pragma unroll
                    for (int hf = 0; hf < 2; hf++) {
                        float* c = acc[mt][ng * 2 + hf];
                        mma16816(c, ahi[mt], bhi[ng][hf * 2], bhi[ng][hf * 2 + 1]);
                        mma16816(c, ahi[mt], blo[ng][hf * 2], blo[ng][hf * 2 + 1]);
                        mma16816(c, alo[mt], bhi[ng][hf * 2], bhi[ng][hf * 2 + 1]);
                    }
        }
        __syncthreads();
    }

    // epilogue: C fragment -> g_h (fp32) + g_hh (fp16)
    int grp = lane >> 2;
    int tg = lane & 3;
#pragma unroll
    for (int mt = 0; mt < 2; mt++) {
#pragma unroll
        for (int nt = 0; nt < 8; nt++) {
            int row = node0 + wm * 32 + mt * 16 + grp;
            int col = wn * 64 + nt * 8 + tg * 2;
            float* c = acc[mt][nt];
            if (row < NN) {
                *(float2*)(g_h + (long)row * OUT_C + col) = make_float2(c[0], c[1]);
                *(__half2*)(g_hh + (long)row * OUT_C + col) = __floats2half2_rn(c[0], c[1]);
            }
            if (row + 8 < NN) {
                *(float2*)(g_h + (long)(row + 8) * OUT_C + col) = make_float2(c[2], c[3]);
                *(__half2*)(g_hh + (long)(row + 8) * OUT_C + col) = __floats2half2_rn(c[2], c[3]);
            }
        }
    }
}

// ---------------------------------------------------------------------------
// el/er: per (node, head) dot of h row-chunk with attn vectors (L2-resident)
// ---------------------------------------------------------------------------
__global__ void elr_kernel(const float* __restrict__ al, const float* __restrict__ ar) {
    int i = blockIdx.x * blockDim.x + threadIdx.x;   // node*NH + head
    if (i >= NN * NH) return;
    int node = i >> 2;
    int head = i & 3;
    const float* hp = g_h + (long)node * OUT_C + head * 32;
    float sl = 0.f, sr = 0.f;
#pragma unroll
    for (int j = 0; j < 8; j++) {
        float4 v = *(const float4*)(hp + j * 4);
        float4 a = *(const float4*)(al + head * 32 + j * 4);
        float4 b = *(const float4*)(ar + head * 32 + j * 4);
        sl += v.x * a.x + v.y * a.y + v.z * a.z + v.w * a.w;
        sr += v.x * b.x + v.y * b.y + v.z * b.z + v.w * b.w;
    }
    g_el[i] = sl;
    g_er[i] = sr;
}

// ---------------------------------------------------------------------------
// Fused softmax + aggregation, warp per destination node, NO atomics.
// Max-subtraction skipped (|e| <~ 13, exp finite, ratios invariant);
// normalization deferred: out = (sum_e exp(e)*h[src]) / (sum_e exp(e)).
// h gathered in fp16 (halves L2 traffic), accumulated in fp32.
// ---------------------------------------------------------------------------
__global__ __launch_bounds__(256) void agg_kernel(const float* __restrict__ bias,
                                                  float* __restrict__ out)
{
    __shared__ float4 s_ex[8][32];
    __shared__ int    s_src[8][32];

    int wib  = threadIdx.x >> 5;
    int lane = threadIdx.x & 31;
    int node = blockIdx.x * 8 + wib;
    if (node >= NN) return;

    int beg = g_off[node];
    int end = g_off[node + 1];
    const float4 er4 = *(const float4*)(g_er + node * NH);

    float4 dsum = make_float4(0.f, 0.f, 0.f, 0.f);
    float4 acc  = make_float4(0.f, 0.f, 0.f, 0.f);
    int hd = lane >> 3;

    for (int c = beg; c < end; c += 32) {
        int n = end - c;
        if (n > 32) n = 32;

        float4 v = make_float4(0.f, 0.f, 0.f, 0.f);
        int s = 0;
        if (lane < n) {
            s = g_csr_src[c + lane];
            float4 L = *(const float4*)(g_el + s * NH);
            v.x = L.x + er4.x; v.y = L.y + er4.y;
            v.z = L.z + er4.z; v.w = L.w + er4.w;
            v.x = v.x >= 0.f ? v.x : NEG * v.x;
            v.y = v.y >= 0.f ? v.y : NEG * v.y;
            v.z = v.z >= 0.f ? v.z : NEG * v.z;
            v.w = v.w >= 0.f ? v.w : NEG * v.w;
            v.x = __expf(v.x); v.y = __expf(v.y);
            v.z = __expf(v.z); v.w = __expf(v.w);
            dsum.x += v.x; dsum.y += v.y; dsum.z += v.z; dsum.w += v.w;
        }
        s_ex[wib][lane] = v;
        s_src[wib][lane] = s;
        __syncwarp();

        if (n == 32) {
#pragma unroll 8
            for (int j = 0; j < 32; j++) {
                int sj = s_src[wib][j];
                float4 ex = s_ex[wib][j];
                float a = (hd == 0) ? ex.x : (hd == 1) ? ex.y : (hd == 2) ? ex.z : ex.w;
                uint2 hv = *(const uint2*)((const char*)g_hh + ((long)sj * OUT_C + lane * 4) * 2);
                float2 f0 = __half22float2(*(const __half2*)&hv.x);
                float2 f1 = __half22float2(*(const __half2*)&hv.y);
                acc.x += f0.x * a; acc.y += f0.y * a;
                acc.z += f1.x * a; acc.w += f1.y * a;
            }
        } else {
            for (int j = 0; j < n; j++) {
                int sj = s_src[wib][j];
                float4 ex = s_ex[wib][j];
                float a = (hd == 0) ? ex.x : (hd == 1) ? ex.y : (hd == 2) ? ex.z : ex.w;
                uint2 hv = *(const uint2*)((const char*)g_hh + ((long)sj * OUT_C + lane * 4) * 2);
                float2 f0 = __half22float2(*(const __half2*)&hv.x);
                float2 f1 = __half22float2(*(const __half2*)&hv.y);
                acc.x += f0.x * a; acc.y += f0.y * a;
                acc.z += f1.x * a; acc.w += f1.y * a;
            }
        }
        __syncwarp();
    }

#pragma unroll
    for (int o = 16; o; o >>= 1) {
        dsum.x += __shfl_xor_sync(0xffffffffu, dsum.x, o);
        dsum.y += __shfl_xor_sync(0xffffffffu, dsum.y, o);
        dsum.z += __shfl_xor_sync(0xffffffffu, dsum.z, o);
        dsum.w += __shfl_xor_sync(0xffffffffu, dsum.w, o);
    }
    float dn = (hd == 0) ? dsum.x : (hd == 1) ? dsum.y : (hd == 2) ? dsum.z : dsum.w;
    float rdn = (dn > 0.f) ? (1.0f / dn) : 1.0f;

    const float4 b4 = *(const float4*)(bias + lane * 4);
    float4 o4;
    o4.x = acc.x * rdn + b4.x;
    o4.y = acc.y * rdn + b4.y;
    o4.z = acc.z * rdn + b4.z;
    o4.w = acc.w * rdn + b4.w;
    *(float4*)(out + (long)node * OUT_C + lane * 4) = o4;
}

// ---------------------------------------------------------------------------
extern "C" void kernel_launch(void* const* d_in, const int* in_sizes, int n_in,
                              void* d_out, int out_size) {
    const float* feat = (const float*)d_in[0];
    const float* W    = (const float*)d_in[1];
    const float* al   = (const float*)d_in[2];
    const float* ar   = (const float*)d_in[3];
    const float* bias = (const float*)d_in[4];
    const int*   src  = (const int*)d_in[5];
    const int*   dst  = (const int*)d_in[6];
    float* out = (float*)d_out;

    zero_cnt_kernel<<<(NN + 255) / 256, 256>>>();
    hist_kernel<<<(NE / 4 + 255) / 256, 256>>>(dst);
    scan_kernel<<<1, 1024>>>();
    scatter_kernel<<<(NE / 4 + 255) / 256, 256>>>(src, dst);
    proj_mma_kernel<<<(NN + 127) / 128, 256>>>(feat, W);
    elr_kernel<<<(NN * NH + 255) / 256, 256>>>(al, ar);
    agg_kernel<<<(NN + 7) / 8, 256>>>(bias, out);
}

// round 7
// speedup vs baseline: 1.5220x; 1.0492x over previous
#include <cuda_runtime.h>
#include <cuda_bf16.h>
#include <cuda_fp16.h>
#include <cstdint>

#define NN 50000
#define NE 1600000
#define IN_F 256
#define OUT_C 128   // H*F
#define NH 4
#define NEG 0.2f

// scratch (allocation-free rule: __device__ globals)
__device__ __align__(16) float  g_h[NN * OUT_C];     // projected features fp32 [N,128]
__device__ __align__(16) __half g_hh[NN * OUT_C];    // fp16 copy for gather   [N,128]
__device__ __align__(16) float  g_el[NN * NH];       // left logits  [N,4]
__device__ __align__(16) float  g_er[NN * NH];       // right logits [N,4]
__device__ int g_cnt[NN];                            // in-degree histogram
__device__ int g_off[NN + 1];                        // CSR offsets (by dst)
__device__ int g_rank[NE];                           // edge rank within its dst
__device__ int g_csr_src[NE];                        // src node per CSR slot

// ---------------------------------------------------------------------------
// CSR build: zero -> hist(+rank) -> scan -> scatter (atomic-free scatter)
// ILP=8: 8 independent edges per thread keep 8 atomics/loads in flight.
// ---------------------------------------------------------------------------
#define EILP 8

__global__ void zero_cnt_kernel() {
    int i = blockIdx.x * blockDim.x + threadIdx.x;
    if (i < NN) g_cnt[i] = 0;
}

__global__ void hist_kernel(const int* __restrict__ dst) {
    int base = (blockIdx.x * blockDim.x + threadIdx.x) * EILP;
    int d[EILP], r[EILP];
#pragma unroll
    for (int j = 0; j < EILP; j++) {
        int e = base + j;
        if (e < NE) d[j] = dst[e];
    }
#pragma unroll
    for (int j = 0; j < EILP; j++)
        if (base + j < NE) r[j] = atomicAdd(&g_cnt[d[j]], 1);
#pragma unroll
    for (int j = 0; j < EILP; j++)
        if (base + j < NE) g_rank[base + j] = r[j];
}

__global__ __launch_bounds__(1024) void scan_kernel() {
    __shared__ int ssum[1024];
    const int CH = (NN + 1023) / 1024;  // 49
    int t = threadIdx.x;
    int b = t * CH;
    int e = min(b + CH, NN);
    int s = 0;
    for (int i = b; i < e; i++) s += g_cnt[i];
    ssum[t] = s;
    __syncthreads();
    for (int off = 1; off < 1024; off <<= 1) {
        int v = (t >= off) ? ssum[t - off] : 0;
        __syncthreads();
        ssum[t] += v;
        __syncthreads();
    }
    int run = ssum[t] - s;
    for (int i = b; i < e; i++) {
        int c = g_cnt[i];
        g_off[i] = run;
        run += c;
    }
    if (t == 1023) g_off[NN] = NE;
}

__global__ void scatter_kernel(const int* __restrict__ src, const int* __restrict__ dst) {
    int base = (blockIdx.x * blockDim.x + threadIdx.x) * EILP;
    int d[EILP], s[EILP], r[EILP], o[EILP];
#pragma unroll
    for (int j = 0; j < EILP; j++) {
        int e = base + j;
        if (e < NE) { d[j] = dst[e]; s[j] = src[e]; r[j] = g_rank[e]; }
    }
#pragma unroll
    for (int j = 0; j < EILP; j++)
        if (base + j < NE) o[j] = g_off[d[j]];
#pragma unroll
    for (int j = 0; j < EILP; j++)
        if (base + j < NE) g_csr_src[o[j] + r[j]] = s[j];
}

// ---------------------------------------------------------------------------
// Projection: h = feat @ W^T via bf16-split tensor-core GEMM.
// A = Ahi+Alo, B = Bhi+Blo (bf16);  C ~= Ahi*Bhi + Ahi*Blo + Alo*Bhi  (err ~2^-18)
// Block tile 128x128, K-step 32, 8 warps (4m x 2n), warp tile 32x64.
// smem pitch 40 bf16 (80 B) -> conflict-free ldmatrix.
// ---------------------------------------------------------------------------
#define SPIT 40

__device__ __forceinline__ void bsplit(float x, __nv_bfloat16& hi, __nv_bfloat16& lo) {
    hi = __float2bfloat16_rn(x);
    lo = __float2bfloat16_rn(x - __bfloat162float(hi));
}

__device__ __forceinline__ void ldm_x4(unsigned* r, const __nv_bfloat16* p) {
    unsigned a = (unsigned)__cvta_generic_to_shared(p);
    asm volatile("ldmatrix.sync.aligned.m8n8.x4.shared.b16 {%0,%1,%2,%3}, [%4];"
                 : "=r"(r[0]), "=r"(r[1]), "=r"(r[2]), "=r"(r[3]) : "r"(a));
}

__device__ __forceinline__ void mma16816(float* c, const unsigned* a,
                                         unsigned b0, unsigned b1) {
    asm volatile("mma.sync.aligned.m16n8k16.row.col.f32.bf16.bf16.f32 "
                 "{%0,%1,%2,%3},{%4,%5,%6,%7},{%8,%9},{%0,%1,%2,%3};"
                 : "+f"(c[0]), "+f"(c[1]), "+f"(c[2]), "+f"(c[3])
                 : "r"(a[0]), "r"(a[1]), "r"(a[2]), "r"(a[3]), "r"(b0), "r"(b1));
}

__global__ __launch_bounds__(256) void proj_mma_kernel(
    const float* __restrict__ feat, const float* __restrict__ W)
{
    __shared__ __nv_bfloat16 sAhi[128][SPIT];
    __shared__ __nv_bfloat16 sAlo[128][SPIT];
    __shared__ __nv_bfloat16 sBhi[128][SPIT];
    __shared__ __nv_bfloat16 sBlo[128][SPIT];

    int t = threadIdx.x;
    int lane = t & 31;
    int wid = t >> 5;
    int wm = wid & 3;
    int wn = wid >> 2;
    int node0 = blockIdx.x * 128;

    float acc[2][8][4];
#pragma unroll
    for (int i = 0; i < 2; i++)
#pragma unroll
        for (int j = 0; j < 8; j++)
#pragma unroll
            for (int q = 0; q < 4; q++) acc[i][j][q] = 0.0f;

    for (int k0 = 0; k0 < IN_F; k0 += 32) {
        // A tile: 128 rows x 32 cols fp32 -> split bf16
#pragma unroll
        for (int j = 0; j < 4; j++) {
            int id = t + j * 256;            // 0..1023
            int row = id >> 3;
            int c4 = (id & 7) * 4;
            int node = node0 + row;
            if (node >= NN) node = NN - 1;
            float4 v = *(const float4*)(feat + (long)node * IN_F + k0 + c4);
            bsplit(v.x, sAhi[row][c4 + 0], sAlo[row][c4 + 0]);
            bsplit(v.y, sAhi[row][c4 + 1], sAlo[row][c4 + 1]);
            bsplit(v.z, sAhi[row][c4 + 2], sAlo[row][c4 + 2]);
            bsplit(v.w, sAhi[row][c4 + 3], sAlo[row][c4 + 3]);
        }
        // B tile: W rows are output cols, exactly 128
#pragma unroll
        for (int j = 0; j < 4; j++) {
            int id = t + j * 256;
            int row = id >> 3;
            int c4 = (id & 7) * 4;
            float4 v = *(const float4*)(W + (long)row * IN_F + k0 + c4);
            bsplit(v.x, sBhi[row][c4 + 0], sBlo[row][c4 + 0]);
            bsplit(v.y, sBhi[row][c4 + 1], sBlo[row][c4 + 1]);
            bsplit(v.z, sBhi[row][c4 + 2], sBlo[row][c4 + 2]);
            bsplit(v.w, sBhi[row][c4 + 3], sBlo[row][c4 + 3]);
        }
        __syncthreads();

#pragma unroll
        for (int ks = 0; ks < 2; ks++) {
            int koff = ks * 16;
            unsigned ahi[2][4], alo[2][4];
#pragma unroll
            for (int mt = 0; mt < 2; mt++) {
                int row = wm * 32 + mt * 16 + (lane & 15);
                int col = koff + (lane >> 4) * 8;
                ldm_x4(ahi[mt], &sAhi[row][col]);
                ldm_x4(alo[mt], &sAlo[row][col]);
            }
            unsigned bhi[4][4], blo[4][4];
#pragma unroll
            for (int ng = 0; ng < 4; ng++) {
                int row = wn * 64 + ng * 16 + (lane & 7) + ((lane >> 4) << 3);
                int col = koff + ((lane >> 3) & 1) * 8;
                ldm_x4(bhi[ng], &sBhi[row][col]);
                ldm_x4(blo[ng], &sBlo[row][col]);
            }
#pragma unroll
            for (int mt = 0; mt < 2; mt++)
#pragma unroll
                for (int ng = 0; ng < 4; ng++)
#pragma unroll
                    for (int hf = 0; hf < 2; hf++) {
                        float* c = acc[mt][ng * 2 + hf];
                        mma16816(c, ahi[mt], bhi[ng][hf * 2], bhi[ng][hf * 2 + 1]);
                        mma16816(c, ahi[mt], blo[ng][hf * 2], blo[ng][hf * 2 + 1]);
                        mma16816(c, alo[mt], bhi[ng][hf * 2], bhi[ng][hf * 2 + 1]);
                    }
        }
        __syncthreads();
    }

    // epilogue: C fragment -> g_h (fp32) + g_hh (fp16)
    int grp = lane >> 2;
    int tg = lane & 3;
#pragma unroll
    for (int mt = 0; mt < 2; mt++) {
#pragma unroll
        for (int nt = 0; nt < 8; nt++) {
            int row = node0 + wm * 32 + mt * 16 + grp;
            int col = wn * 64 + nt * 8 + tg * 2;
            float* c = acc[mt][nt];
            if (row < NN) {
                *(float2*)(g_h + (long)row * OUT_C + col) = make_float2(c[0], c[1]);
                *(__half2*)(g_hh + (long)row * OUT_C + col) = __floats2half2_rn(c[0], c[1]);
            }
            if (row + 8 < NN) {
                *(float2*)(g_h + (long)(row + 8) * OUT_C + col) = make_float2(c[2], c[3]);
                *(__half2*)(g_hh + (long)(row + 8) * OUT_C + col) = __floats2half2_rn(c[2], c[3]);
            }
        }
    }
}

// ---------------------------------------------------------------------------
// el/er: per (node, head) dot of h row-chunk with attn vectors (L2-resident)
// ---------------------------------------------------------------------------
__global__ void elr_kernel(const float* __restrict__ al, const float* __restrict__ ar) {
    int i = blockIdx.x * blockDim.x + threadIdx.x;   // node*NH + head
    if (i >= NN * NH) return;
    int node = i >> 2;
    int head = i & 3;
    const float* hp = g_h + (long)node * OUT_C + head * 32;
    float sl = 0.f, sr = 0.f;
#pragma unroll
    for (int j = 0; j < 8; j++) {
        float4 v = *(const float4*)(hp + j * 4);
        float4 a = *(const float4*)(al + head * 32 + j * 4);
        float4 b = *(const float4*)(ar + head * 32 + j * 4);
        sl += v.x * a.x + v.y * a.y + v.z * a.z + v.w * a.w;
        sr += v.x * b.x + v.y * b.y + v.z * b.z + v.w * b.w;
    }
    g_el[i] = sl;
    g_er[i] = sr;
}

// ---------------------------------------------------------------------------
// Fused softmax + aggregation, warp per destination node, NO atomics.
// Max-subtraction skipped (|e| <~ 13, exp finite, ratios invariant);
// normalization deferred: out = (sum_e exp(e)*h[src]) / (sum_e exp(e)).
// h gathered in fp16 (halves L2 traffic), accumulated in fp32.
// ---------------------------------------------------------------------------
__global__ __launch_bounds__(256) void agg_kernel(const float* __restrict__ bias,
                                                  float* __restrict__ out)
{
    __shared__ float4 s_ex[8][32];
    __shared__ int    s_src[8][32];

    int wib  = threadIdx.x >> 5;
    int lane = threadIdx.x & 31;
    int node = blockIdx.x * 8 + wib;
    if (node >= NN) return;

    int beg = g_off[node];
    int end = g_off[node + 1];
    const float4 er4 = *(const float4*)(g_er + node * NH);

    float4 dsum = make_float4(0.f, 0.f, 0.f, 0.f);
    float4 acc  = make_float4(0.f, 0.f, 0.f, 0.f);
    int hd = lane >> 3;

    for (int c = beg; c < end; c += 32) {
        int n = end - c;
        if (n > 32) n = 32;

        float4 v = make_float4(0.f, 0.f, 0.f, 0.f);
        int s = 0;
        if (lane < n) {
            s = g_csr_src[c + lane];
            float4 L = *(const float4*)(g_el + s * NH);
            v.x = L.x + er4.x; v.y = L.y + er4.y;
            v.z = L.z + er4.z; v.w = L.w + er4.w;
            v.x = v.x >= 0.f ? v.x : NEG * v.x;
            v.y = v.y >= 0.f ? v.y : NEG * v.y;
            v.z = v.z >= 0.f ? v.z : NEG * v.z;
            v.w = v.w >= 0.f ? v.w : NEG * v.w;
            v.x = __expf(v.x); v.y = __expf(v.y);
            v.z = __expf(v.z); v.w = __expf(v.w);
            dsum.x += v.x; dsum.y += v.y; dsum.z += v.z; dsum.w += v.w;
        }
        s_ex[wib][lane] = v;
        s_src[wib][lane] = s;
        __syncwarp();

        if (n == 32) {
#pragma unroll 8
            for (int j = 0; j < 32; j++) {
                int sj = s_src[wib][j];
                float4 ex = s_ex[wib][j];
                float a = (hd == 0) ? ex.x : (hd == 1) ? ex.y : (hd == 2) ? ex.z : ex.w;
                uint2 hv = *(const uint2*)((const char*)g_hh + ((long)sj * OUT_C + lane * 4) * 2);
                float2 f0 = __half22float2(*(const __half2*)&hv.x);
                float2 f1 = __half22float2(*(const __half2*)&hv.y);
                acc.x += f0.x * a; acc.y += f0.y * a;
                acc.z += f1.x * a; acc.w += f1.y * a;
            }
        } else {
            for (int j = 0; j < n; j++) {
                int sj = s_src[wib][j];
                float4 ex = s_ex[wib][j];
                float a = (hd == 0) ? ex.x : (hd == 1) ? ex.y : (hd == 2) ? ex.z : ex.w;
                uint2 hv = *(const uint2*)((const char*)g_hh + ((long)sj * OUT_C + lane * 4) * 2);
                float2 f0 = __half22float2(*(const __half2*)&hv.x);
                float2 f1 = __half22float2(*(const __half2*)&hv.y);
                acc.x += f0.x * a; acc.y += f0.y * a;
                acc.z += f1.x * a; acc.w += f1.y * a;
            }
        }
        __syncwarp();
    }

#pragma unroll
    for (int o = 16; o; o >>= 1) {
        dsum.x += __shfl_xor_sync(0xffffffffu, dsum.x, o);
        dsum.y += __shfl_xor_sync(0xffffffffu, dsum.y, o);
        dsum.z += __shfl_xor_sync(0xffffffffu, dsum.z, o);
        dsum.w += __shfl_xor_sync(0xffffffffu, dsum.w, o);
    }
    float dn = (hd == 0) ? dsum.x : (hd == 1) ? dsum.y : (hd == 2) ? dsum.z : dsum.w;
    float rdn = (dn > 0.f) ? (1.0f / dn) : 1.0f;

    const float4 b4 = *(const float4*)(bias + lane * 4);
    float4 o4;
    o4.x = acc.x * rdn + b4.x;
    o4.y = acc.y * rdn + b4.y;
    o4.z = acc.z * rdn + b4.z;
    o4.w = acc.w * rdn + b4.w;
    *(float4*)(out + (long)node * OUT_C + lane * 4) = o4;
}

// ---------------------------------------------------------------------------
// Launch: fork-join so the CSR build (stream s2, atomic/latency-bound) overlaps
// the projection GEMM (main stream, tensor/smem-bound). Streams/events are
// created once on first call (resource init, not work-skipping); all captured
// ops are launches + event record/wait, which are graph-capturable.
// ---------------------------------------------------------------------------
extern "C" void kernel_launch(void* const* d_in, const int* in_sizes, int n_in,
                              void* d_out, int out_size) {
    const float* feat = (const float*)d_in[0];
    const float* W    = (const float*)d_in[1];
    const float* al   = (const float*)d_in[2];
    const float* ar   = (const float*)d_in[3];
    const float* bias = (const float*)d_in[4];
    const int*   src  = (const int*)d_in[5];
    const int*   dst  = (const int*)d_in[6];
    float* out = (float*)d_out;

    static cudaStream_t s2 = nullptr;
    static cudaEvent_t ev_fork = nullptr, ev_join = nullptr;
    if (s2 == nullptr) {
        cudaStreamCreateWithFlags(&s2, cudaStreamNonBlocking);
        cudaEventCreateWithFlags(&ev_fork, cudaEventDisableTiming);
        cudaEventCreateWithFlags(&ev_join, cudaEventDisableTiming);
    }

    // fork: s2 joins the capture via the event dependency
    cudaEventRecord(ev_fork, 0);
    cudaStreamWaitEvent(s2, ev_fork, 0);

    // branch A (s2): CSR build
    zero_cnt_kernel<<<(NN + 255) / 256, 256, 0, s2>>>();
    hist_kernel<<<(NE / EILP + 255) / 256, 256, 0, s2>>>(dst);
    scan_kernel<<<1, 1024, 0, s2>>>();
    scatter_kernel<<<(NE / EILP + 255) / 256, 256, 0, s2>>>(src, dst);

    // branch B (main stream): projection + logits
    proj_mma_kernel<<<(NN + 127) / 128, 256>>>(feat, W);
    elr_kernel<<<(NN * NH + 255) / 256, 256>>>(al, ar);

    // join
    cudaEventRecord(ev_join, s2);
    cudaStreamWaitEvent(0, ev_join, 0);

    agg_kernel<<<(NN + 7) / 8, 256>>>(bias, out);
}

// round 8
// speedup vs baseline: 1.7083x; 1.1224x over previous
#include <cuda_runtime.h>
#include <cuda_bf16.h>
#include <cuda_fp16.h>
#include <cstdint>

#define NN 50000
#define NE 1600000
#define IN_F 256
#define OUT_C 128   // H*F
#define NH 4
#define NEG 0.2f

// scratch (allocation-free rule: __device__ globals)
__device__ __align__(16) float  g_h[NN * OUT_C];     // projected features fp32 [N,128]
__device__ __align__(16) __half g_hh[NN * OUT_C];    // fp16 copy for gather   [N,128]
__device__ __align__(16) float  g_el[NN * NH];       // left logits  [N,4]
__device__ __align__(16) float  g_er[NN * NH];       // right logits [N,4]
__device__ int g_cnt[NN];                            // in-degree histogram
__device__ int g_off[NN + 1];                        // CSR offsets (by dst)
__device__ int g_rank[NE];                           // edge rank within its dst
__device__ int g_csr_src[NE];                        // src node per CSR slot

// ---------------------------------------------------------------------------
// CSR build: zero -> hist(+rank) -> scan -> scatter (atomic-free scatter)
// ---------------------------------------------------------------------------
#define EILP 8

__global__ void zero_cnt_kernel() {
    int i = blockIdx.x * blockDim.x + threadIdx.x;
    if (i < NN) g_cnt[i] = 0;
}

__global__ void hist_kernel(const int* __restrict__ dst) {
    int base = (blockIdx.x * blockDim.x + threadIdx.x) * EILP;
    int d[EILP], r[EILP];
#pragma unroll
    for (int j = 0; j < EILP; j++) {
        int e = base + j;
        if (e < NE) d[j] = dst[e];
    }
#pragma unroll
    for (int j = 0; j < EILP; j++)
        if (base + j < NE) r[j] = atomicAdd(&g_cnt[d[j]], 1);
#pragma unroll
    for (int j = 0; j < EILP; j++)
        if (base + j < NE) g_rank[base + j] = r[j];
}

__global__ __launch_bounds__(1024) void scan_kernel() {
    __shared__ int ssum[1024];
    const int CH = (NN + 1023) / 1024;  // 49
    int t = threadIdx.x;
    int b = t * CH;
    int e = min(b + CH, NN);
    int s = 0;
    for (int i = b; i < e; i++) s += g_cnt[i];
    ssum[t] = s;
    __syncthreads();
    for (int off = 1; off < 1024; off <<= 1) {
        int v = (t >= off) ? ssum[t - off] : 0;
        __syncthreads();
        ssum[t] += v;
        __syncthreads();
    }
    int run = ssum[t] - s;
    for (int i = b; i < e; i++) {
        int c = g_cnt[i];
        g_off[i] = run;
        run += c;
    }
    if (t == 1023) g_off[NN] = NE;
}

__global__ void scatter_kernel(const int* __restrict__ src, const int* __restrict__ dst) {
    int base = (blockIdx.x * blockDim.x + threadIdx.x) * EILP;
    int d[EILP], s[EILP], r[EILP], o[EILP];
#pragma unroll
    for (int j = 0; j < EILP; j++) {
        int e = base + j;
        if (e < NE) { d[j] = dst[e]; s[j] = src[e]; r[j] = g_rank[e]; }
    }
#pragma unroll
    for (int j = 0; j < EILP; j++)
        if (base + j < NE) o[j] = g_off[d[j]];
#pragma unroll
    for (int j = 0; j < EILP; j++)
        if (base + j < NE) g_csr_src[o[j] + r[j]] = s[j];
}

// ---------------------------------------------------------------------------
// Projection: h = feat @ W^T via bf16-split tensor-core GEMM.
// A = Ahi+Alo, B = Bhi+Blo (bf16);  C ~= Ahi*Bhi + Ahi*Blo + Alo*Bhi  (err ~2^-18)
// Block tile 128x128, K-step 32, 8 warps (4m x 2n), warp tile 32x64.
// smem pitch 40 bf16 (80 B) -> conflict-free ldmatrix.
// ---------------------------------------------------------------------------
#define SPIT 40

__device__ __forceinline__ void bsplit(float x, __nv_bfloat16& hi, __nv_bfloat16& lo) {
    hi = __float2bfloat16_rn(x);
    lo = __float2bfloat16_rn(x - __bfloat162float(hi));
}

__device__ __forceinline__ void ldm_x4(unsigned* r, const __nv_bfloat16* p) {
    unsigned a = (unsigned)__cvta_generic_to_shared(p);
    asm volatile("ldmatrix.sync.aligned.m8n8.x4.shared.b16 {%0,%1,%2,%3}, [%4];"
                 : "=r"(r[0]), "=r"(r[1]), "=r"(r[2]), "=r"(r[3]) : "r"(a));
}

__device__ __forceinline__ void mma16816(float* c, const unsigned* a,
                                         unsigned b0, unsigned b1) {
    asm volatile("mma.sync.aligned.m16n8k16.row.col.f32.bf16.bf16.f32 "
                 "{%0,%1,%2,%3},{%4,%5,%6,%7},{%8,%9},{%0,%1,%2,%3};"
                 : "+f"(c[0]), "+f"(c[1]), "+f"(c[2]), "+f"(c[3])
                 : "r"(a[0]), "r"(a[1]), "r"(a[2]), "r"(a[3]), "r"(b0), "r"(b1));
}

__global__ __launch_bounds__(256) void proj_mma_kernel(
    const float* __restrict__ feat, const float* __restrict__ W)
{
    __shared__ __nv_bfloat16 sAhi[128][SPIT];
    __shared__ __nv_bfloat16 sAlo[128][SPIT];
    __shared__ __nv_bfloat16 sBhi[128][SPIT];
    __shared__ __nv_bfloat16 sBlo[128][SPIT];

    int t = threadIdx.x;
    int lane = t & 31;
    int wid = t >> 5;
    int wm = wid & 3;
    int wn = wid >> 2;
    int node0 = blockIdx.x * 128;

    float acc[2][8][4];
#pragma unroll
    for (int i = 0; i < 2; i++)
#pragma unroll
        for (int j = 0; j < 8; j++)
#pragma unroll
            for (int q = 0; q < 4; q++) acc[i][j][q] = 0.0f;

    for (int k0 = 0; k0 < IN_F; k0 += 32) {
        // A tile: 128 rows x 32 cols fp32 -> split bf16
#pragma unroll
        for (int j = 0; j < 4; j++) {
            int id = t + j * 256;            // 0..1023
            int row = id >> 3;
            int c4 = (id & 7) * 4;
            int node = node0 + row;
            if (node >= NN) node = NN - 1;
            float4 v = *(const float4*)(feat + (long)node * IN_F + k0 + c4);
            bsplit(v.x, sAhi[row][c4 + 0], sAlo[row][c4 + 0]);
            bsplit(v.y, sAhi[row][c4 + 1], sAlo[row][c4 + 1]);
            bsplit(v.z, sAhi[row][c4 + 2], sAlo[row][c4 + 2]);
            bsplit(v.w, sAhi[row][c4 + 3], sAlo[row][c4 + 3]);
        }
        // B tile: W rows are output cols, exactly 128
#pragma unroll
        for (int j = 0; j < 4; j++) {
            int id = t + j * 256;
            int row = id >> 3;
            int c4 = (id & 7) * 4;
            float4 v = *(const float4*)(W + (long)row * IN_F + k0 + c4);
            bsplit(v.x, sBhi[row][c4 + 0], sBlo[row][c4 + 0]);
            bsplit(v.y, sBhi[row][c4 + 1], sBlo[row][c4 + 1]);
            bsplit(v.z, sBhi[row][c4 + 2], sBlo[row][c4 + 2]);
            bsplit(v.w, sBhi[row][c4 + 3], sBlo[row][c4 + 3]);
        }
        __syncthreads();

#pragma unroll
        for (int ks = 0; ks < 2; ks++) {
            int koff = ks * 16;
            unsigned ahi[2][4], alo[2][4];
#pragma unroll
            for (int mt = 0; mt < 2; mt++) {
                int row = wm * 32 + mt * 16 + (lane & 15);
                int col = koff + (lane >> 4) * 8;
                ldm_x4(ahi[mt], &sAhi[row][col]);
                ldm_x4(alo[mt], &sAlo[row][col]);
            }
            unsigned bhi[4][4], blo[4][4];
#pragma unroll
            for (int ng = 0; ng < 4; ng++) {
                int row = wn * 64 + ng * 16 + (lane & 7) + ((lane >> 4) << 3);
                int col = koff + ((lane >> 3) & 1) * 8;
                ldm_x4(bhi[ng], &sBhi[row][col]);
                ldm_x4(blo[ng], &sBlo[row][col]);
            }
#pragma unroll
            for (int mt = 0; mt < 2; mt++)
#pragma unroll
                for (int ng = 0; ng < 4; ng++)
#pragma unroll
                    for (int hf = 0; hf < 2; hf++) {
                        float* c = acc[mt][ng * 2 + hf];
                        mma16816(c, ahi[mt], bhi[ng][hf * 2], bhi[ng][hf * 2 + 1]);
                        mma16816(c, ahi[mt], blo[ng][hf * 2], blo[ng][hf * 2 + 1]);
                        mma16816(c, alo[mt], bhi[ng][hf * 2], bhi[ng][hf * 2 + 1]);
                    }
        }
        __syncthreads();
    }

    // epilogue: C fragment -> g_h (fp32) + g_hh (fp16)
    int grp = lane >> 2;
    int tg = lane & 3;
#pragma unroll
    for (int mt = 0; mt < 2; mt++) {
#pragma unroll
        for (int nt = 0; nt < 8; nt++) {
            int row = node0 + wm * 32 + mt * 16 + grp;
            int col = wn * 64 + nt * 8 + tg * 2;
            float* c = acc[mt][nt];
            if (row < NN) {
                *(float2*)(g_h + (long)row * OUT_C + col) = make_float2(c[0], c[1]);
                *(__half2*)(g_hh + (long)row * OUT_C + col) = __floats2half2_rn(c[0], c[1]);
            }
            if (row + 8 < NN) {
                *(float2*)(g_h + (long)(row + 8) * OUT_C + col) = make_float2(c[2], c[3]);
                *(__half2*)(g_hh + (long)(row + 8) * OUT_C + col) = __floats2half2_rn(c[2], c[3]);
            }
        }
    }
}

// ---------------------------------------------------------------------------
// el/er: per (node, head) dot of h row-chunk with attn vectors (L2-resident)
// ---------------------------------------------------------------------------
__global__ void elr_kernel(const float* __restrict__ al, const float* __restrict__ ar) {
    int i = blockIdx.x * blockDim.x + threadIdx.x;   // node*NH + head
    if (i >= NN * NH) return;
    int node = i >> 2;
    int head = i & 3;
    const float* hp = g_h + (long)node * OUT_C + head * 32;
    float sl = 0.f, sr = 0.f;
#pragma unroll
    for (int j = 0; j < 8; j++) {
        float4 v = *(const float4*)(hp + j * 4);
        float4 a = *(const float4*)(al + head * 32 + j * 4);
        float4 b = *(const float4*)(ar + head * 32 + j * 4);
        sl += v.x * a.x + v.y * a.y + v.z * a.z + v.w * a.w;
        sr += v.x * b.x + v.y * b.y + v.z * b.z + v.w * b.w;
    }
    g_el[i] = sl;
    g_er[i] = sr;
}

// ---------------------------------------------------------------------------
// Fused softmax + aggregation, warp per destination node, NO atomics.
// Gather phase: HALF-WARP per edge (2 edges in flight), uint4 fp16 loads.
// Each lane covers 8 consecutive fp16 cols [hl*8, hl*8+8), head = hl/4.
// Halves merged with one shfl_xor(16) at the end.
// ---------------------------------------------------------------------------
__global__ __launch_bounds__(256) void agg_kernel(const float* __restrict__ bias,
                                                  float* __restrict__ out)
{
    __shared__ float4 s_ex[8][32];
    __shared__ int    s_src[8][32];

    int wib  = threadIdx.x >> 5;
    int lane = threadIdx.x & 31;
    int node = blockIdx.x * 8 + wib;
    if (node >= NN) return;

    int beg = g_off[node];
    int end = g_off[node + 1];
    const float4 er4 = *(const float4*)(g_er + node * NH);

    int half = lane >> 4;      // which edge of the pair
    int hl   = lane & 15;      // lane within half-warp
    int hd2  = hl >> 2;        // head for my column range

    float4 dsum = make_float4(0.f, 0.f, 0.f, 0.f);
    float acc8[8];
#pragma unroll
    for (int k = 0; k < 8; k++) acc8[k] = 0.f;

    for (int c = beg; c < end; c += 32) {
        int n = end - c;
        if (n > 32) n = 32;

        // score phase: lane-parallel edge scores (1 edge per lane)
        float4 v = make_float4(0.f, 0.f, 0.f, 0.f);
        int s = 0;
        if (lane < n) {
            s = g_csr_src[c + lane];
            float4 L = *(const float4*)(g_el + s * NH);
            v.x = L.x + er4.x; v.y = L.y + er4.y;
            v.z = L.z + er4.z; v.w = L.w + er4.w;
            v.x = v.x >= 0.f ? v.x : NEG * v.x;
            v.y = v.y >= 0.f ? v.y : NEG * v.y;
            v.z = v.z >= 0.f ? v.z : NEG * v.z;
            v.w = v.w >= 0.f ? v.w : NEG * v.w;
            v.x = __expf(v.x); v.y = __expf(v.y);
            v.z = __expf(v.z); v.w = __expf(v.w);
            dsum.x += v.x; dsum.y += v.y; dsum.z += v.z; dsum.w += v.w;
        }
        s_ex[wib][lane] = v;
        s_src[wib][lane] = s;
        __syncwarp();

        // gather phase: 2 edges per iteration (half-warp each), uint4 loads
        if (n == 32) {
#pragma unroll
            for (int j0 = 0; j0 < 32; j0 += 2) {
                int j = j0 + half;
                int sj = s_src[wib][j];
                float4 ex = s_ex[wib][j];
                float a = (hd2 == 0) ? ex.x : (hd2 == 1) ? ex.y : (hd2 == 2) ? ex.z : ex.w;
                uint4 hv = *(const uint4*)((const char*)g_hh + ((long)sj * OUT_C + hl * 8) * 2);
                float2 f0 = __half22float2(*(const __half2*)&hv.x);
                float2 f1 = __half22float2(*(const __half2*)&hv.y);
                float2 f2 = __half22float2(*(const __half2*)&hv.z);
                float2 f3 = __half22float2(*(const __half2*)&hv.w);
                acc8[0] += f0.x * a; acc8[1] += f0.y * a;
                acc8[2] += f1.x * a; acc8[3] += f1.y * a;
                acc8[4] += f2.x * a; acc8[5] += f2.y * a;
                acc8[6] += f3.x * a; acc8[7] += f3.y * a;
            }
        } else {
            for (int j0 = 0; j0 < n; j0 += 2) {
                int j = j0 + half;
                if (j < n) {
                    int sj = s_src[wib][j];
                    float4 ex = s_ex[wib][j];
                    float a = (hd2 == 0) ? ex.x : (hd2 == 1) ? ex.y : (hd2 == 2) ? ex.z : ex.w;
                    uint4 hv = *(const uint4*)((const char*)g_hh + ((long)sj * OUT_C + hl * 8) * 2);
                    float2 f0 = __half22float2(*(const __half2*)&hv.x);
                    float2 f1 = __half22float2(*(const __half2*)&hv.y);
                    float2 f2 = __half22float2(*(const __half2*)&hv.z);
                    float2 f3 = __half22float2(*(const __half2*)&hv.w);
                    acc8[0] += f0.x * a; acc8[1] += f0.y * a;
                    acc8[2] += f1.x * a; acc8[3] += f1.y * a;
                    acc8[4] += f2.x * a; acc8[5] += f2.y * a;
                    acc8[6] += f3.x * a; acc8[7] += f3.y * a;
                }
            }
        }
        __syncwarp();
    }

    // merge the two half-warp partial sums (same columns at lane ^ 16)
#pragma unroll
    for (int k = 0; k < 8; k++)
        acc8[k] += __shfl_xor_sync(0xffffffffu, acc8[k], 16);

    // reduce denominators across the warp
#pragma unroll
    for (int o = 16; o; o >>= 1) {
        dsum.x += __shfl_xor_sync(0xffffffffu, dsum.x, o);
        dsum.y += __shfl_xor_sync(0xffffffffu, dsum.y, o);
        dsum.z += __shfl_xor_sync(0xffffffffu, dsum.z, o);
        dsum.w += __shfl_xor_sync(0xffffffffu, dsum.w, o);
    }

    if (half == 0) {
        float dn = (hd2 == 0) ? dsum.x : (hd2 == 1) ? dsum.y : (hd2 == 2) ? dsum.z : dsum.w;
        float rdn = (dn > 0.f) ? (1.0f / dn) : 1.0f;
        float4 b0 = *(const float4*)(bias + hl * 8);
        float4 b1 = *(const float4*)(bias + hl * 8 + 4);
        float4 o0, o1;
        o0.x = acc8[0] * rdn + b0.x; o0.y = acc8[1] * rdn + b0.y;
        o0.z = acc8[2] * rdn + b0.z; o0.w = acc8[3] * rdn + b0.w;
        o1.x = acc8[4] * rdn + b1.x; o1.y = acc8[5] * rdn + b1.y;
        o1.z = acc8[6] * rdn + b1.z; o1.w = acc8[7] * rdn + b1.w;
        *(float4*)(out + (long)node * OUT_C + hl * 8)     = o0;
        *(float4*)(out + (long)node * OUT_C + hl * 8 + 4) = o1;
    }
}

// ---------------------------------------------------------------------------
// Launch: fork-join so the CSR build (stream s2, atomic/latency-bound) overlaps
// the projection GEMM (main stream, tensor/smem-bound).
// ---------------------------------------------------------------------------
extern "C" void kernel_launch(void* const* d_in, const int* in_sizes, int n_in,
                              void* d_out, int out_size) {
    const float* feat = (const float*)d_in[0];
    const float* W    = (const float*)d_in[1];
    const float* al   = (const float*)d_in[2];
    const float* ar   = (const float*)d_in[3];
    const float* bias = (const float*)d_in[4];
    const int*   src  = (const int*)d_in[5];
    const int*   dst  = (const int*)d_in[6];
    float* out = (float*)d_out;

    static cudaStream_t s2 = nullptr;
    static cudaEvent_t ev_fork = nullptr, ev_join = nullptr;
    if (s2 == nullptr) {
        cudaStreamCreateWithFlags(&s2, cudaStreamNonBlocking);
        cudaEventCreateWithFlags(&ev_fork, cudaEventDisableTiming);
        cudaEventCreateWithFlags(&ev_join, cudaEventDisableTiming);
    }

    // fork: s2 joins the capture via the event dependency
    cudaEventRecord(ev_fork, 0);
    cudaStreamWaitEvent(s2, ev_fork, 0);

    // branch A (s2): CSR build
    zero_cnt_kernel<<<(NN + 255) / 256, 256, 0, s2>>>();
    hist_kernel<<<(NE / EILP + 255) / 256, 256, 0, s2>>>(dst);
    scan_kernel<<<1, 1024, 0, s2>>>();
    scatter_kernel<<<(NE / EILP + 255) / 256, 256, 0, s2>>>(src, dst);

    // branch B (main stream): projection + logits
    proj_mma_kernel<<<(NN + 127) / 128, 256>>>(feat, W);
    elr_kernel<<<(NN * NH + 255) / 256, 256>>>(al, ar);

    // join
    cudaEventRecord(ev_join, s2);
    cudaStreamWaitEvent(0, ev_join, 0);

    agg_kernel<<<(NN + 7) / 8, 256>>>(bias, out);
}

// round 10
// speedup vs baseline: 1.7241x; 1.0093x over previous
#include <cuda_runtime.h>
#include <cuda_bf16.h>
#include <cuda_fp16.h>
#include <cstdint>

#define NN 50000
#define NE 1600000
#define IN_F 256
#define OUT_C 128   // H*F
#define NH 4
#define NEG 0.2f

// scratch (allocation-free rule: __device__ globals)
__device__ __align__(16) float  g_h[NN * OUT_C];     // projected features fp32 [N,128]
__device__ __align__(16) __half g_hh[NN * OUT_C];    // fp16 copy for gather   [N,128]
__device__ __align__(16) float  g_el[NN * NH];       // left logits  [N,4]
__device__ __align__(16) float  g_er[NN * NH];       // right logits [N,4]
__device__ int g_cnt[NN];                            // in-degree histogram
__device__ int g_off[NN + 1];                        // CSR offsets (by dst)
__device__ __align__(16) int g_rank[NE];             // edge rank within its dst
__device__ int g_csr_src[NE];                        // src node per CSR slot

// ---------------------------------------------------------------------------
// CSR build: zero -> hist(+rank) -> scan -> scatter (atomic-free scatter)
// NE % 8 == 0: one guard per thread, int4-vectorized edge loads.
// ---------------------------------------------------------------------------
__global__ void zero_cnt_kernel() {
    int i = blockIdx.x * blockDim.x + threadIdx.x;
    if (i < NN) g_cnt[i] = 0;
}

__global__ void hist_kernel(const int* __restrict__ dst) {
    int base = (blockIdx.x * blockDim.x + threadIdx.x) * 8;
    if (base >= NE) return;
    int4 d0 = *(const int4*)(dst + base);
    int4 d1 = *(const int4*)(dst + base + 4);
    int d[8] = {d0.x, d0.y, d0.z, d0.w, d1.x, d1.y, d1.z, d1.w};
    int r[8];
#pragma unroll
    for (int j = 0; j < 8; j++) r[j] = atomicAdd(&g_cnt[d[j]], 1);
    *(int4*)(g_rank + base)     = make_int4(r[0], r[1], r[2], r[3]);
    *(int4*)(g_rank + base + 4) = make_int4(r[4], r[5], r[6], r[7]);
}

__global__ __launch_bounds__(1024) void scan_kernel() {
    __shared__ int ssum[1024];
    const int CH = (NN + 1023) / 1024;  // 49
    int t = threadIdx.x;
    int b = t * CH;
    int e = min(b + CH, NN);
    int s = 0;
    for (int i = b; i < e; i++) s += g_cnt[i];
    ssum[t] = s;
    __syncthreads();
    for (int off = 1; off < 1024; off <<= 1) {
        int v = (t >= off) ? ssum[t - off] : 0;
        __syncthreads();
        ssum[t] += v;
        __syncthreads();
    }
    int run = ssum[t] - s;
    for (int i = b; i < e; i++) {
        int c = g_cnt[i];
        g_off[i] = run;
        run += c;
    }
    if (t == 1023) g_off[NN] = NE;
}

__global__ void scatter_kernel(const int* __restrict__ src, const int* __restrict__ dst) {
    int base = (blockIdx.x * blockDim.x + threadIdx.x) * 8;
    if (base >= NE) return;
    int4 d0 = *(const int4*)(dst + base);
    int4 d1 = *(const int4*)(dst + base + 4);
    int4 s0 = *(const int4*)(src + base);
    int4 s1 = *(const int4*)(src + base + 4);
    int4 r0 = *(const int4*)(g_rank + base);
    int4 r1 = *(const int4*)(g_rank + base + 4);
    int d[8] = {d0.x, d0.y, d0.z, d0.w, d1.x, d1.y, d1.z, d1.w};
    int s[8] = {s0.x, s0.y, s0.z, s0.w, s1.x, s1.y, s1.z, s1.w};
    int r[8] = {r0.x, r0.y, r0.z, r0.w, r1.x, r1.y, r1.z, r1.w};
    int o[8];
#pragma unroll
    for (int j = 0; j < 8; j++) o[j] = g_off[d[j]];
#pragma unroll
    for (int j = 0; j < 8; j++) g_csr_src[o[j] + r[j]] = s[j];
}

// ---------------------------------------------------------------------------
// Projection: h = feat @ W^T via bf16-split tensor-core GEMM.
// A = Ahi+Alo, B = Bhi+Blo (bf16);  C ~= Ahi*Bhi + Ahi*Blo + Alo*Bhi  (err ~2^-18)
// Block tile 128x128, K-step 32, 8 warps (4m x 2n), warp tile 32x64.
// smem pitch 40 bf16 (80 B) -> conflict-free ldmatrix.
// ---------------------------------------------------------------------------
#define SPIT 40

__device__ __forceinline__ void bsplit(float x, __nv_bfloat16& hi, __nv_bfloat16& lo) {
    hi = __float2bfloat16_rn(x);
    lo = __float2bfloat16_rn(x - __bfloat162float(hi));
}

__device__ __forceinline__ void ldm_x4(unsigned* r, const __nv_bfloat16* p) {
    unsigned a = (unsigned)__cvta_generic_to_shared(p);
    asm volatile("ldmatrix.sync.aligned.m8n8.x4.shared.b16 {%0,%1,%2,%3}, [%4];"
                 : "=r"(r[0]), "=r"(r[1]), "=r"(r[2]), "=r"(r[3]) : "r"(a));
}

__device__ __forceinline__ void mma16816(float* c, const unsigned* a,
                                         unsigned b0, unsigned b1) {
    asm volatile("mma.sync.aligned.m16n8k16.row.col.f32.bf16.bf16.f32 "
                 "{%0,%1,%2,%3},{%4,%5,%6,%7},{%8,%9},{%0,%1,%2,%3};"
                 : "+f"(c[0]), "+f"(c[1]), "+f"(c[2]), "+f"(c[3])
                 : "r"(a[0]), "r"(a[1]), "r"(a[2]), "r"(a[3]), "r"(b0), "r"(b1));
}

__global__ __launch_bounds__(256) void proj_mma_kernel(
    const float* __restrict__ feat, const float* __restrict__ W)
{
    __shared__ __nv_bfloat16 sAhi[128][SPIT];
    __shared__ __nv_bfloat16 sAlo[128][SPIT];
    __shared__ __nv_bfloat16 sBhi[128][SPIT];
    __shared__ __nv_bfloat16 sBlo[128][SPIT];

    int t = threadIdx.x;
    int lane = t & 31;
    int wid = t >> 5;
    int wm = wid & 3;
    int wn = wid >> 2;
    int node0 = blockIdx.x * 128;

    float acc[2][8][4];
#pragma unroll
    for (int i = 0; i < 2; i++)
#pragma unroll
        for (int j = 0; j < 8; j++)
#pragma unroll
            for (int q = 0; q < 4; q++) acc[i][j][q] = 0.0f;

    for (int k0 = 0; k0 < IN_F; k0 += 32) {
        // A tile: 128 rows x 32 cols fp32 -> split bf16
#pragma unroll
        for (int j = 0; j < 4; j++) {
            int id = t + j * 256;            // 0..1023
            int row = id >> 3;
            int c4 = (id & 7) * 4;
            int node = node0 + row;
            if (node >= NN) node = NN - 1;
            float4 v = *(const float4*)(feat + (long)node * IN_F + k0 + c4);
            bsplit(v.x, sAhi[row][c4 + 0], sAlo[row][c4 + 0]);
            bsplit(v.y, sAhi[row][c4 + 1], sAlo[row][c4 + 1]);
            bsplit(v.z, sAhi[row][c4 + 2], sAlo[row][c4 + 2]);
            bsplit(v.w, sAhi[row][c4 + 3], sAlo[row][c4 + 3]);
        }
        // B tile: W rows are output cols, exactly 128
#pragma unroll
        for (int j = 0; j < 4; j++) {
            int id = t + j * 256;
            int row = id >> 3;
            int c4 = (id & 7) * 4;
            float4 v = *(const float4*)(W + (long)row * IN_F + k0 + c4);
            bsplit(v.x, sBhi[row][c4 + 0], sBlo[row][c4 + 0]);
            bsplit(v.y, sBhi[row][c4 + 1], sBlo[row][c4 + 1]);
            bsplit(v.z, sBhi[row][c4 + 2], sBlo[row][c4 + 2]);
            bsplit(v.w, sBhi[row][c4 + 3], sBlo[row][c4 + 3]);
        }
        __syncthreads();

#pragma unroll
        for (int ks = 0; ks < 2; ks++) {
            int koff = ks * 16;
            unsigned ahi[2][4], alo[2][4];
#pragma unroll
            for (int mt = 0; mt < 2; mt++) {
                int row = wm * 32 + mt * 16 + (lane & 15);
                int col = koff + (lane >> 4) * 8;
                ldm_x4(ahi[mt], &sAhi[row][col]);
                ldm_x4(alo[mt], &sAlo[row][col]);
            }
            unsigned bhi[4][4], blo[4][4];
#pragma unroll
            for (int ng = 0; ng < 4; ng++) {
                int row = wn * 64 + ng * 16 + (lane & 7) + ((lane >> 4) << 3);
                int col = koff + ((lane >> 3) & 1) * 8;
                ldm_x4(bhi[ng], &sBhi[row][col]);
                ldm_x4(blo[ng], &sBlo[row][col]);
            }
#pragma unroll
            for (int mt = 0; mt < 2; mt++)
#pragma unroll
                for (int ng = 0; ng < 4; ng++)
#pragma unroll
                    for (int hf = 0; hf < 2; hf++) {
                        float* c = acc[mt][ng * 2 + hf];
                        mma16816(c, ahi[mt], bhi[ng][hf * 2], bhi[ng][hf * 2 + 1]);
                        mma16816(c, ahi[mt], blo[ng][hf * 2], blo[ng][hf * 2 + 1]);
                        mma16816(c, alo[mt], bhi[ng][hf * 2], bhi[ng][hf * 2 + 1]);
                    }
        }
        __syncthreads();
    }

    // epilogue: C fragment -> g_h (fp32) + g_hh (fp16)
    int grp = lane >> 2;
    int tg = lane & 3;
#pragma unroll
    for (int mt = 0; mt < 2; mt++) {
#pragma unroll
        for (int nt = 0; nt < 8; nt++) {
            int row = node0 + wm * 32 + mt * 16 + grp;
            int col = wn * 64 + nt * 8 + tg * 2;
            float* c = acc[mt][nt];
            if (row < NN) {
                *(float2*)(g_h + (long)row * OUT_C + col) = make_float2(c[0], c[1]);
                *(__half2*)(g_hh + (long)row * OUT_C + col) = __floats2half2_rn(c[0], c[1]);
            }
            if (row + 8 < NN) {
                *(float2*)(g_h + (long)(row + 8) * OUT_C + col) = make_float2(c[2], c[3]);
                *(__half2*)(g_hh + (long)(row + 8) * OUT_C + col) = __floats2half2_rn(c[2], c[3]);
            }
        }
    }
}

// ---------------------------------------------------------------------------
// el/er: per (node, head) dot of h row-chunk with attn vectors (L2-resident)
// ---------------------------------------------------------------------------
__global__ void elr_kernel(const float* __restrict__ al, const float* __restrict__ ar) {
    int i = blockIdx.x * blockDim.x + threadIdx.x;   // node*NH + head
    if (i >= NN * NH) return;
    int node = i >> 2;
    int head = i & 3;
    const float* hp = g_h + (long)node * OUT_C + head * 32;
    float sl = 0.f, sr = 0.f;
#pragma unroll
    for (int j = 0; j < 8; j++) {
        float4 v = *(const float4*)(hp + j * 4);
        float4 a = *(const float4*)(al + head * 32 + j * 4);
        float4 b = *(const float4*)(ar + head * 32 + j * 4);
        sl += v.x * a.x + v.y * a.y + v.z * a.z + v.w * a.w;
        sr += v.x * b.x + v.y * b.y + v.z * b.z + v.w * b.w;
    }
    g_el[i] = sl;
    g_er[i] = sr;
}

// ---------------------------------------------------------------------------
// Fused softmax + aggregation, warp per destination node, NO atomics.
// Gather: half-warp per edge, uint4 fp16 loads, EXPLICIT 4-deep load batching
// (8 edges in flight per warp) to force MLP against L2 latency.
// ---------------------------------------------------------------------------
__global__ __launch_bounds__(256) void agg_kernel(const float* __restrict__ bias,
                                                  float* __restrict__ out)
{
    __shared__ float4 s_ex[8][32];
    __shared__ int    s_src[8][32];

    int wib  = threadIdx.x >> 5;
    int lane = threadIdx.x & 31;
    int node = blockIdx.x * 8 + wib;
    if (node >= NN) return;

    int beg = g_off[node];
    int end = g_off[node + 1];
    const float4 er4 = *(const float4*)(g_er + node * NH);

    int half = lane >> 4;      // which edge of the pair
    int hl   = lane & 15;      // lane within half-warp
    int hd2  = hl >> 2;        // head for my column range

    float4 dsum = make_float4(0.f, 0.f, 0.f, 0.f);
    float acc8[8];
#pragma unroll
    for (int k = 0; k < 8; k++) acc8[k] = 0.f;

    for (int c = beg; c < end; c += 32) {
        int n = end - c;
        if (n > 32) n = 32;

        // score phase: lane-parallel edge scores (1 edge per lane)
        float4 v = make_float4(0.f, 0.f, 0.f, 0.f);
        int s = 0;
        if (lane < n) {
            s = g_csr_src[c + lane];
            float4 L = *(const float4*)(g_el + s * NH);
            v.x = L.x + er4.x; v.y = L.y + er4.y;
            v.z = L.z + er4.z; v.w = L.w + er4.w;
            v.x = v.x >= 0.f ? v.x : NEG * v.x;
            v.y = v.y >= 0.f ? v.y : NEG * v.y;
            v.z = v.z >= 0.f ? v.z : NEG * v.z;
            v.w = v.w >= 0.f ? v.w : NEG * v.w;
            v.x = __expf(v.x); v.y = __expf(v.y);
            v.z = __expf(v.z); v.w = __expf(v.w);
            dsum.x += v.x; dsum.y += v.y; dsum.z += v.z; dsum.w += v.w;
        }
        s_ex[wib][lane] = v;
        s_src[wib][lane] = s;
        __syncwarp();

        // gather phase
        if (n == 32) {
#pragma unroll
            for (int j0 = 0; j0 < 32; j0 += 8) {
                uint4 hv[4];
                float av[4];
#pragma unroll
                for (int b = 0; b < 4; b++) {
                    int j = j0 + b * 2 + half;
                    int sj = s_src[wib][j];
                    float4 ex = s_ex[wib][j];
                    av[b] = (hd2 == 0) ? ex.x : (hd2 == 1) ? ex.y : (hd2 == 2) ? ex.z : ex.w;
                    hv[b] = *(const uint4*)((const char*)g_hh + ((long)sj * OUT_C + hl * 8) * 2);
                }
#pragma unroll
                for (int b = 0; b < 4; b++) {
                    float a = av[b];
                    float2 f0 = __half22float2(*(const __half2*)&hv[b].x);
                    float2 f1 = __half22float2(*(const __half2*)&hv[b].y);
                    float2 f2 = __half22float2(*(const __half2*)&hv[b].z);
                    float2 f3 = __half22float2(*(const __half2*)&hv[b].w);
                    acc8[0] += f0.x * a; acc8[1] += f0.y * a;
                    acc8[2] += f1.x * a; acc8[3] += f1.y * a;
                    acc8[4] += f2.x * a; acc8[5] += f2.y * a;
                    acc8[6] += f3.x * a; acc8[7] += f3.y * a;
                }
            }
        } else {
            for (int j0 = 0; j0 < n; j0 += 2) {
                int j = j0 + half;
                if (j < n) {
                    int sj = s_src[wib][j];
                    float4 ex = s_ex[wib][j];
                    float a = (hd2 == 0) ? ex.x : (hd2 == 1) ? ex.y : (hd2 == 2) ? ex.z : ex.w;
                    uint4 hv = *(const uint4*)((const char*)g_hh + ((long)sj * OUT_C + hl * 8) * 2);
                    float2 f0 = __half22float2(*(const __half2*)&hv.x);
                    float2 f1 = __half22float2(*(const __half2*)&hv.y);
                    float2 f2 = __half22float2(*(const __half2*)&hv.z);
                    float2 f3 = __half22float2(*(const __half2*)&hv.w);
                    acc8[0] += f0.x * a; acc8[1] += f0.y * a;
                    acc8[2] += f1.x * a; acc8[3] += f1.y * a;
                    acc8[4] += f2.x * a; acc8[5] += f2.y * a;
                    acc8[6] += f3.x * a; acc8[7] += f3.y * a;
                }
            }
        }
        __syncwarp();
    }

    // merge the two half-warp partial sums (same columns at lane ^ 16)
#pragma unroll
    for (int k = 0; k < 8; k++)
        acc8[k] += __shfl_xor_sync(0xffffffffu, acc8[k], 16);

    // reduce denominators across the warp
#pragma unroll
    for (int o = 16; o; o >>= 1) {
        dsum.x += __shfl_xor_sync(0xffffffffu, dsum.x, o);
        dsum.y += __shfl_xor_sync(0xffffffffu, dsum.y, o);
        dsum.z += __shfl_xor_sync(0xffffffffu, dsum.z, o);
        dsum.w += __shfl_xor_sync(0xffffffffu, dsum.w, o);
    }

    if (half == 0) {
        float dn = (hd2 == 0) ? dsum.x : (hd2 == 1) ? dsum.y : (hd2 == 2) ? dsum.z : dsum.w;
        float rdn = (dn > 0.f) ? (1.0f / dn) : 1.0f;
        float4 b0 = *(const float4*)(bias + hl * 8);
        float4 b1 = *(const float4*)(bias + hl * 8 + 4);
        float4 o0, o1;
        o0.x = acc8[0] * rdn + b0.x; o0.y = acc8[1] * rdn + b0.y;
        o0.z = acc8[2] * rdn + b0.z; o0.w = acc8[3] * rdn + b0.w;
        o1.x = acc8[4] * rdn + b1.x; o1.y = acc8[5] * rdn + b1.y;
        o1.z = acc8[6] * rdn + b1.z; o1.w = acc8[7] * rdn + b1.w;
        *(float4*)(out + (long)node * OUT_C + hl * 8)     = o0;
        *(float4*)(out + (long)node * OUT_C + hl * 8 + 4) = o1;
    }
}

// ---------------------------------------------------------------------------
// Launch: fork-join so the CSR build (stream s2, atomic/latency-bound) overlaps
// the projection GEMM (main stream, tensor/smem-bound).
// ---------------------------------------------------------------------------
extern "C" void kernel_launch(void* const* d_in, const int* in_sizes, int n_in,
                              void* d_out, int out_size) {
    const float* feat = (const float*)d_in[0];
    const float* W    = (const float*)d_in[1];
    const float* al   = (const float*)d_in[2];
    const float* ar   = (const float*)d_in[3];
    const float* bias = (const float*)d_in[4];
    const int*   src  = (const int*)d_in[5];
    const int*   dst  = (const int*)d_in[6];
    float* out = (float*)d_out;

    static cudaStream_t s2 = nullptr;
    static cudaEvent_t ev_fork = nullptr, ev_join = nullptr;
    if (s2 == nullptr) {
        cudaStreamCreateWithFlags(&s2, cudaStreamNonBlocking);
        cudaEventCreateWithFlags(&ev_fork, cudaEventDisableTiming);
        cudaEventCreateWithFlags(&ev_join, cudaEventDisableTiming);
    }

    // fork: s2 joins the capture via the event dependency
    cudaEventRecord(ev_fork, 0);
    cudaStreamWaitEvent(s2, ev_fork, 0);

    // branch A (s2): CSR build
    zero_cnt_kernel<<<(NN + 255) / 256, 256, 0, s2>>>();
    hist_kernel<<<(NE / 8 + 255) / 256, 256, 0, s2>>>(dst);
    scan_kernel<<<1, 1024, 0, s2>>>();
    scatter_kernel<<<(NE / 8 + 255) / 256, 256, 0, s2>>>(src, dst);

    // branch B (main stream): projection + logits
    proj_mma_kernel<<<(NN + 127) / 128, 256>>>(feat, W);
    elr_kernel<<<(NN * NH + 255) / 256, 256>>>(al, ar);

    // join
    cudaEventRecord(ev_join, s2);
    cudaStreamWaitEvent(0, ev_join, 0);

    agg_kernel<<<(NN + 7) / 8, 256>>>(bias, out);
}

// round 11
// speedup vs baseline: 1.8906x; 1.0966x over previous
#include <cuda_runtime.h>
#include <cuda_bf16.h>
#include <cuda_fp16.h>
#include <cstdint>

#define NN 50000
#define NE 1600000
#define IN_F 256
#define OUT_C 128   // H*F
#define NH 4
#define NEG 0.2f

// scratch (allocation-free rule: __device__ globals)
__device__ __align__(16) float  g_h[NN * OUT_C];     // projected features fp32 [N,128]
__device__ __align__(16) __half g_hh[NN * OUT_C];    // fp16 copy for gather   [N,128]
__device__ __align__(16) float  g_el[NN * NH];       // left logits  [N,4]
__device__ __align__(16) float  g_er[NN * NH];       // right logits [N,4]
__device__ int g_cnt[NN];                            // in-degree histogram
__device__ int g_off[NN + 1];                        // CSR offsets (by dst)
__device__ __align__(16) int g_rank[NE];             // edge rank within its dst
__device__ int g_csr_src[NE];                        // src node per CSR slot

// ---------------------------------------------------------------------------
// CSR build: zero -> hist(+rank) -> scan -> scatter (atomic-free scatter)
// NE % 8 == 0: one guard per thread, int4-vectorized edge loads.
// ---------------------------------------------------------------------------
__global__ void zero_cnt_kernel() {
    int i = blockIdx.x * blockDim.x + threadIdx.x;
    if (i < NN) g_cnt[i] = 0;
}

__global__ void hist_kernel(const int* __restrict__ dst) {
    int base = (blockIdx.x * blockDim.x + threadIdx.x) * 8;
    if (base >= NE) return;
    int4 d0 = *(const int4*)(dst + base);
    int4 d1 = *(const int4*)(dst + base + 4);
    int d[8] = {d0.x, d0.y, d0.z, d0.w, d1.x, d1.y, d1.z, d1.w};
    int r[8];
#pragma unroll
    for (int j = 0; j < 8; j++) r[j] = atomicAdd(&g_cnt[d[j]], 1);
    *(int4*)(g_rank + base)     = make_int4(r[0], r[1], r[2], r[3]);
    *(int4*)(g_rank + base + 4) = make_int4(r[4], r[5], r[6], r[7]);
}

__global__ __launch_bounds__(1024) void scan_kernel() {
    __shared__ int ssum[1024];
    const int CH = (NN + 1023) / 1024;  // 49
    int t = threadIdx.x;
    int b = t * CH;
    int e = min(b + CH, NN);
    int s = 0;
    for (int i = b; i < e; i++) s += g_cnt[i];
    ssum[t] = s;
    __syncthreads();
    for (int off = 1; off < 1024; off <<= 1) {
        int v = (t >= off) ? ssum[t - off] : 0;
        __syncthreads();
        ssum[t] += v;
        __syncthreads();
    }
    int run = ssum[t] - s;
    for (int i = b; i < e; i++) {
        int c = g_cnt[i];
        g_off[i] = run;
        run += c;
    }
    if (t == 1023) g_off[NN] = NE;
}

__global__ void scatter_kernel(const int* __restrict__ src, const int* __restrict__ dst) {
    int base = (blockIdx.x * blockDim.x + threadIdx.x) * 8;
    if (base >= NE) return;
    int4 d0 = *(const int4*)(dst + base);
    int4 d1 = *(const int4*)(dst + base + 4);
    int4 s0 = *(const int4*)(src + base);
    int4 s1 = *(const int4*)(src + base + 4);
    int4 r0 = *(const int4*)(g_rank + base);
    int4 r1 = *(const int4*)(g_rank + base + 4);
    int d[8] = {d0.x, d0.y, d0.z, d0.w, d1.x, d1.y, d1.z, d1.w};
    int s[8] = {s0.x, s0.y, s0.z, s0.w, s1.x, s1.y, s1.z, s1.w};
    int r[8] = {r0.x, r0.y, r0.z, r0.w, r1.x, r1.y, r1.z, r1.w};
    int o[8];
#pragma unroll
    for (int j = 0; j < 8; j++) o[j] = g_off[d[j]];
#pragma unroll
    for (int j = 0; j < 8; j++) g_csr_src[o[j] + r[j]] = s[j];
}

// ---------------------------------------------------------------------------
// Projection: h = feat @ W^T via bf16-split tensor-core GEMM.
// A = Ahi+Alo, B = Bhi+Blo (bf16);  C ~= Ahi*Bhi + Ahi*Blo + Alo*Bhi  (err ~2^-18)
// Block tile 128x128, K-step 32, 8 warps (4m x 2n), warp tile 32x64.
// smem pitch 40 bf16 (80 B) -> conflict-free ldmatrix.
// ---------------------------------------------------------------------------
#define SPIT 40

__device__ __forceinline__ void bsplit(float x, __nv_bfloat16& hi, __nv_bfloat16& lo) {
    hi = __float2bfloat16_rn(x);
    lo = __float2bfloat16_rn(x - __bfloat162float(hi));
}

__device__ __forceinline__ void ldm_x4(unsigned* r, const __nv_bfloat16* p) {
    unsigned a = (unsigned)__cvta_generic_to_shared(p);
    asm volatile("ldmatrix.sync.aligned.m8n8.x4.shared.b16 {%0,%1,%2,%3}, [%4];"
                 : "=r"(r[0]), "=r"(r[1]), "=r"(r[2]), "=r"(r[3]) : "r"(a));
}

__device__ __forceinline__ void mma16816(float* c, const unsigned* a,
                                         unsigned b0, unsigned b1) {
    asm volatile("mma.sync.aligned.m16n8k16.row.col.f32.bf16.bf16.f32 "
                 "{%0,%1,%2,%3},{%4,%5,%6,%7},{%8,%9},{%0,%1,%2,%3};"
                 : "+f"(c[0]), "+f"(c[1]), "+f"(c[2]), "+f"(c[3])
                 : "r"(a[0]), "r"(a[1]), "r"(a[2]), "r"(a[3]), "r"(b0), "r"(b1));
}

__global__ __launch_bounds__(256) void proj_mma_kernel(
    const float* __restrict__ feat, const float* __restrict__ W)
{
    __shared__ __nv_bfloat16 sAhi[128][SPIT];
    __shared__ __nv_bfloat16 sAlo[128][SPIT];
    __shared__ __nv_bfloat16 sBhi[128][SPIT];
    __shared__ __nv_bfloat16 sBlo[128][SPIT];

    int t = threadIdx.x;
    int lane = t & 31;
    int wid = t >> 5;
    int wm = wid & 3;
    int wn = wid >> 2;
    int node0 = blockIdx.x * 128;

    float acc[2][8][4];
#pragma unroll
    for (int i = 0; i < 2; i++)
#pragma unroll
        for (int j = 0; j < 8; j++)
#pragma unroll
            for (int q = 0; q < 4; q++) acc[i][j][q] = 0.0f;

    for (int k0 = 0; k0 < IN_F; k0 += 32) {
        // A tile: 128 rows x 32 cols fp32 -> split bf16
#pragma unroll
        for (int j = 0; j < 4; j++) {
            int id = t + j * 256;            // 0..1023
            int row = id >> 3;
            int c4 = (id & 7) * 4;
            int node = node0 + row;
            if (node >= NN) node = NN - 1;
            float4 v = *(const float4*)(feat + (long)node * IN_F + k0 + c4);
            bsplit(v.x, sAhi[row][c4 + 0], sAlo[row][c4 + 0]);
            bsplit(v.y, sAhi[row][c4 + 1], sAlo[row][c4 + 1]);
            bsplit(v.z, sAhi[row][c4 + 2], sAlo[row][c4 + 2]);
            bsplit(v.w, sAhi[row][c4 + 3], sAlo[row][c4 + 3]);
        }
        // B tile: W rows are output cols, exactly 128
#pragma unroll
        for (int j = 0; j < 4; j++) {
            int id = t + j * 256;
            int row = id >> 3;
            int c4 = (id & 7) * 4;
            float4 v = *(const float4*)(W + (long)row * IN_F + k0 + c4);
            bsplit(v.x, sBhi[row][c4 + 0], sBlo[row][c4 + 0]);
            bsplit(v.y, sBhi[row][c4 + 1], sBlo[row][c4 + 1]);
            bsplit(v.z, sBhi[row][c4 + 2], sBlo[row][c4 + 2]);
            bsplit(v.w, sBhi[row][c4 + 3], sBlo[row][c4 + 3]);
        }
        __syncthreads();

#pragma unroll
        for (int ks = 0; ks < 2; ks++) {
            int koff = ks * 16;
            unsigned ahi[2][4], alo[2][4];
#pragma unroll
            for (int mt = 0; mt < 2; mt++) {
                int row = wm * 32 + mt * 16 + (lane & 15);
                int col = koff + (lane >> 4) * 8;
                ldm_x4(ahi[mt], &sAhi[row][col]);
                ldm_x4(alo[mt], &sAlo[row][col]);
            }
            unsigned bhi[4][4], blo[4][4];
#pragma unroll
            for (int ng = 0; ng < 4; ng++) {
                int row = wn * 64 + ng * 16 + (lane & 7) + ((lane >> 4) << 3);
                int col = koff + ((lane >> 3) & 1) * 8;
                ldm_x4(bhi[ng], &sBhi[row][col]);
                ldm_x4(blo[ng], &sBlo[row][col]);
            }
#pragma unroll
            for (int mt = 0; mt < 2; mt++)
#pragma unroll
                for (int ng = 0; ng < 4; ng++)
#pragma unroll
                    for (int hf = 0; hf < 2; hf++) {
                        float* c = acc[mt][ng * 2 + hf];
                        mma16816(c, ahi[mt], bhi[ng][hf * 2], bhi[ng][hf * 2 + 1]);
                        mma16816(c, ahi[mt], blo[ng][hf * 2], blo[ng][hf * 2 + 1]);
                        mma16816(c, alo[mt], bhi[ng][hf * 2], bhi[ng][hf * 2 + 1]);
                    }
        }
        __syncthreads();
    }

    // epilogue: C fragment -> g_h (fp32) + g_hh (fp16)
    int grp = lane >> 2;
    int tg = lane & 3;
#pragma unroll
    for (int mt = 0; mt < 2; mt++) {
#pragma unroll
        for (int nt = 0; nt < 8; nt++) {
            int row = node0 + wm * 32 + mt * 16 + grp;
            int col = wn * 64 + nt * 8 + tg * 2;
            float* c = acc[mt][nt];
            if (row < NN) {
                *(float2*)(g_h + (long)row * OUT_C + col) = make_float2(c[0], c[1]);
                *(__half2*)(g_hh + (long)row * OUT_C + col) = __floats2half2_rn(c[0], c[1]);
            }
            if (row + 8 < NN) {
                *(float2*)(g_h + (long)(row + 8) * OUT_C + col) = make_float2(c[2], c[3]);
                *(__half2*)(g_hh + (long)(row + 8) * OUT_C + col) = __floats2half2_rn(c[2], c[3]);
            }
        }
    }
}

// ---------------------------------------------------------------------------
// el/er: per (node, head) dot of h row-chunk with attn vectors (L2-resident)
// ---------------------------------------------------------------------------
__global__ void elr_kernel(const float* __restrict__ al, const float* __restrict__ ar) {
    int i = blockIdx.x * blockDim.x + threadIdx.x;   // node*NH + head
    if (i >= NN * NH) return;
    int node = i >> 2;
    int head = i & 3;
    const float* hp = g_h + (long)node * OUT_C + head * 32;
    float sl = 0.f, sr = 0.f;
#pragma unroll
    for (int j = 0; j < 8; j++) {
        float4 v = *(const float4*)(hp + j * 4);
        float4 a = *(const float4*)(al + head * 32 + j * 4);
        float4 b = *(const float4*)(ar + head * 32 + j * 4);
        sl += v.x * a.x + v.y * a.y + v.z * a.z + v.w * a.w;
        sr += v.x * b.x + v.y * b.y + v.z * b.z + v.w * b.w;
    }
    g_el[i] = sl;
    g_er[i] = sr;
}

// ---------------------------------------------------------------------------
// Fused softmax + aggregation: single-phase, half-warp per edge.
// All 16 lanes of a half-warp own one edge end-to-end:
//   - g_csr_src[e]: same address for all lanes (broadcast, 1 line)
//   - g_el[s*4+head]: scalar per lane's head (1 line per edge)
//   - one leaky+exp per lane (vs 4 in the 2-phase version)
//   - uint4 fp16 h-row slice + 8 FMAs
// No smem, no __syncwarp, flat unrolled stream of independent edges.
// Denominator: per-lane exp sums reduced over the 8-lane head orbit, /4.
// ---------------------------------------------------------------------------
__global__ __launch_bounds__(256) void agg_kernel(const float* __restrict__ bias,
                                                  float* __restrict__ out)
{
    int wib  = threadIdx.x >> 5;
    int lane = threadIdx.x & 31;
    int node = blockIdx.x * 8 + wib;
    if (node >= NN) return;

    int beg = g_off[node];
    int end = g_off[node + 1];

    int half = lane >> 4;      // which edge of the pair
    int hl   = lane & 15;      // lane within half-warp
    int hd2  = hl >> 2;        // head for my column range

    const float erv = g_er[node * NH + hd2];

    float dsum = 0.f;
    float acc8[8];
#pragma unroll
    for (int k = 0; k < 8; k++) acc8[k] = 0.f;

    const long colo = (long)hl * 8;   // fp16 column offset for this lane

    int e0 = beg;
    // main loop: 4 edges per warp iteration (2 per half-warp)
    for (; e0 + 3 < end; e0 += 4) {
        int eA = e0 + half * 2;
        int sA = g_csr_src[eA];
        int sB = g_csr_src[eA + 1];
        float lA = g_el[sA * NH + hd2];
        float lB = g_el[sB * NH + hd2];
        uint4 hA = *(const uint4*)((const char*)g_hh + ((long)sA * OUT_C + colo) * 2);
        uint4 hB = *(const uint4*)((const char*)g_hh + ((long)sB * OUT_C + colo) * 2);

        float xA = lA + erv; xA = xA >= 0.f ? xA : NEG * xA;
        float xB = lB + erv; xB = xB >= 0.f ? xB : NEG * xB;
        float aA = __expf(xA);
        float aB = __expf(xB);
        dsum += aA + aB;

        float2 f;
        f = __half22float2(*(const __half2*)&hA.x); acc8[0] += f.x * aA; acc8[1] += f.y * aA;
        f = __half22float2(*(const __half2*)&hA.y); acc8[2] += f.x * aA; acc8[3] += f.y * aA;
        f = __half22float2(*(const __half2*)&hA.z); acc8[4] += f.x * aA; acc8[5] += f.y * aA;
        f = __half22float2(*(const __half2*)&hA.w); acc8[6] += f.x * aA; acc8[7] += f.y * aA;
        f = __half22float2(*(const __half2*)&hB.x); acc8[0] += f.x * aB; acc8[1] += f.y * aB;
        f = __half22float2(*(const __half2*)&hB.y); acc8[2] += f.x * aB; acc8[3] += f.y * aB;
        f = __half22float2(*(const __half2*)&hB.z); acc8[4] += f.x * aB; acc8[5] += f.y * aB;
        f = __half22float2(*(const __half2*)&hB.w); acc8[6] += f.x * aB; acc8[7] += f.y * aB;
    }
    // tail: up to 3 edges, parity-split across halves
    for (; e0 < end; e0 += 2) {
        int e = e0 + half;
        if (e < end) {
            int s = g_csr_src[e];
            float l = g_el[s * NH + hd2];
            uint4 hv = *(const uint4*)((const char*)g_hh + ((long)s * OUT_C + colo) * 2);
            float x = l + erv; x = x >= 0.f ? x : NEG * x;
            float a = __expf(x);
            dsum += a;
            float2 f;
            f = __half22float2(*(const __half2*)&hv.x); acc8[0] += f.x * a; acc8[1] += f.y * a;
            f = __half22float2(*(const __half2*)&hv.y); acc8[2] += f.x * a; acc8[3] += f.y * a;
            f = __half22float2(*(const __half2*)&hv.z); acc8[4] += f.x * a; acc8[5] += f.y * a;
            f = __half22float2(*(const __half2*)&hv.w); acc8[6] += f.x * a; acc8[7] += f.y * a;
        }
    }

    // merge the two half-warp partial sums (same columns at lane ^ 16)
#pragma unroll
    for (int k = 0; k < 8; k++)
        acc8[k] += __shfl_xor_sync(0xffffffffu, acc8[k], 16);

    // reduce denominator over the 8-lane same-head orbit (4x replication)
    dsum += __shfl_xor_sync(0xffffffffu, dsum, 16);
    dsum += __shfl_xor_sync(0xffffffffu, dsum, 1);
    dsum += __shfl_xor_sync(0xffffffffu, dsum, 2);
    float dn = dsum * 0.25f;
    float rdn = (dn > 0.f) ? (1.0f / dn) : 1.0f;

    if (half == 0) {
        float4 b0 = *(const float4*)(bias + hl * 8);
        float4 b1 = *(const float4*)(bias + hl * 8 + 4);
        float4 o0, o1;
        o0.x = acc8[0] * rdn + b0.x; o0.y = acc8[1] * rdn + b0.y;
        o0.z = acc8[2] * rdn + b0.z; o0.w = acc8[3] * rdn + b0.w;
        o1.x = acc8[4] * rdn + b1.x; o1.y = acc8[5] * rdn + b1.y;
        o1.z = acc8[6] * rdn + b1.z; o1.w = acc8[7] * rdn + b1.w;
        *(float4*)(out + (long)node * OUT_C + hl * 8)     = o0;
        *(float4*)(out + (long)node * OUT_C + hl * 8 + 4) = o1;
    }
}

// ---------------------------------------------------------------------------
// Launch: fork-join so the CSR build (stream s2, atomic/latency-bound) overlaps
// the projection GEMM (main stream, tensor/smem-bound).
// ---------------------------------------------------------------------------
extern "C" void kernel_launch(void* const* d_in, const int* in_sizes, int n_in,
                              void* d_out, int out_size) {
    const float* feat = (const float*)d_in[0];
    const float* W    = (const float*)d_in[1];
    const float* al   = (const float*)d_in[2];
    const float* ar   = (const float*)d_in[3];
    const float* bias = (const float*)d_in[4];
    const int*   src  = (const int*)d_in[5];
    const int*   dst  = (const int*)d_in[6];
    float* out = (float*)d_out;

    static cudaStream_t s2 = nullptr;
    static cudaEvent_t ev_fork = nullptr, ev_join = nullptr;
    if (s2 == nullptr) {
        cudaStreamCreateWithFlags(&s2, cudaStreamNonBlocking);
        cudaEventCreateWithFlags(&ev_fork, cudaEventDisableTiming);
        cudaEventCreateWithFlags(&ev_join, cudaEventDisableTiming);
    }

    // fork: s2 joins the capture via the event dependency
    cudaEventRecord(ev_fork, 0);
    cudaStreamWaitEvent(s2, ev_fork, 0);

    // branch A (s2): CSR build
    zero_cnt_kernel<<<(NN + 255) / 256, 256, 0, s2>>>();
    hist_kernel<<<(NE / 8 + 255) / 256, 256, 0, s2>>>(dst);
    scan_kernel<<<1, 1024, 0, s2>>>();
    scatter_kernel<<<(NE / 8 + 255) / 256, 256, 0, s2>>>(src, dst);

    // branch B (main stream): projection + logits
    proj_mma_kernel<<<(NN + 127) / 128, 256>>>(feat, W);
    elr_kernel<<<(NN * NH + 255) / 256, 256>>>(al, ar);

    // join
    cudaEventRecord(ev_join, s2);
    cudaStreamWaitEvent(0, ev_join, 0);

    agg_kernel<<<(NN + 7) / 8, 256>>>(bias, out);
}